// round 12
// baseline (speedup 1.0000x reference)
#include <cuda_runtime.h>
#include <cuda_fp16.h>
#include <cstdint>

#define DD 1024
#define HH 4096
#define NB 8
#define LL 768
#define MT 6144   // NB*LL
#define NE 4

#define KCH 64               // K halfs per chunk (128B rows)
#define SS 3                 // pipeline stages
#define TILE_BYTES 16384     // 128 rows x 128B
#define STG_BYTES 32768      // A tile + B tile
#define GEMM_SMEM (SS * STG_BYTES)   // 96 KB -> 2 CTAs/SM
#define KSPLIT 3             // GEMM2 split-K ways

// ---------------- scratch (device globals; no allocation) ----------------
__device__ __align__(256) __half g_Xh[(size_t)MT * DD];
__device__ __align__(256) __half g_W1e[(size_t)NE * HH * DD];  // W1^T per expert: [H][D]
__device__ __align__(256) __half g_W2e[(size_t)NE * DD * HH];  // W2^T per expert: [D][H]
__device__ __align__(256) __half g_W1s[(size_t)HH * DD];       // sw1^T
__device__ __align__(256) __half g_W2s[(size_t)DD * HH];       // sw2^T
__device__ __align__(256) __half g_H[(size_t)5 * MT * HH];     // [shared, e0..e3] hidden
__device__ __align__(256) float  g_P[(size_t)KSPLIT * MT * DD]; // GEMM2 split-K partials
__device__ float  g_partial[NB * 6 * DD];
__device__ float  g_wbe[NB * NE];

// ---------------- helpers ----------------
__device__ __forceinline__ uint32_t smem_u32(const void* p) {
    uint32_t a;
    asm("{ .reg .u64 t; cvta.to.shared.u64 t, %1; cvt.u32.u64 %0, t; }" : "=r"(a) : "l"(p));
    return a;
}
__device__ __forceinline__ void cp_async16(void* smem, const void* gmem) {
    unsigned s = (unsigned)__cvta_generic_to_shared(smem);
    asm volatile("cp.async.cg.shared.global [%0], [%1], 16;\n" :: "r"(s), "l"(gmem) : "memory");
}
__device__ __forceinline__ void cp_commit() { asm volatile("cp.async.commit_group;\n" ::: "memory"); }

__device__ __forceinline__ void ldm4(uint32_t* r, uint32_t addr) {
    asm volatile("ldmatrix.sync.aligned.m8n8.x4.shared.b16 {%0,%1,%2,%3}, [%4];"
        : "=r"(r[0]), "=r"(r[1]), "=r"(r[2]), "=r"(r[3]) : "r"(addr));
}
__device__ __forceinline__ void mma16816(float* c, const uint32_t* a, const uint32_t* b) {
    asm volatile(
        "mma.sync.aligned.m16n8k16.row.col.f32.f16.f16.f32 "
        "{%0,%1,%2,%3}, {%4,%5,%6,%7}, {%8,%9}, {%0,%1,%2,%3};"
        : "+f"(c[0]), "+f"(c[1]), "+f"(c[2]), "+f"(c[3])
        : "r"(a[0]), "r"(a[1]), "r"(a[2]), "r"(a[3]), "r"(b[0]), "r"(b[1]));
}

// fast GELU (tanh approx via single-instruction MUFU tanh)
__device__ __forceinline__ float gelu_t(float v) {
    float c = 0.7978845608028654f * (v + 0.044715f * v * v * v);
    float t;
    asm("tanh.approx.f32 %0, %1;" : "=f"(t) : "f"(c));
    return 0.5f * v * (1.f + t);
}

// per-M-tile weight: batch gating weight x third-mask; exact 0 => skip tile
__device__ __forceinline__ float tile_weight(int expert, int bm) {
    if (expert < 0) return 1.f;
    int b = bm / 6;             // 6 tiles of 128 tokens per batch
    int third = (bm % 6) >> 1;  // 0 head, 1 wrist, 2 proprio
    if (expert == 1 && third == 1) return 0.f;
    if (expert == 2 && third == 0) return 0.f;
    return g_wbe[b * NE + expert];
}

// ---------------- merged conversion + stageA kernel ----------------
__global__ void k_conv(const float* __restrict__ x,
                       const float* __restrict__ ew1, const float* __restrict__ sw1,
                       const float* __restrict__ ew2, const float* __restrict__ sw2)
{
    int z = blockIdx.z;
    int ltid = threadIdx.y * 32 + threadIdx.x;   // 0..255
    if (z == 0) {
        int n4 = MT * DD / 4;
        int stride = gridDim.x * 256;
        for (int i = ltid + blockIdx.x * 256; i < n4; i += stride) {
            float4 v = reinterpret_cast<const float4*>(x)[i];
            __half2* d2 = reinterpret_cast<__half2*>(g_Xh) + (size_t)i * 2;
            d2[0] = __floats2half2_rn(v.x, v.y);
            d2[1] = __floats2half2_rn(v.z, v.w);
        }
        return;
    }
    if (z == 2 * NE + 3) {
        if (blockIdx.x >= NB * 6) return;
        int b = blockIdx.x / 6, c = blockIdx.x % 6;
        const float* base = x + ((size_t)(b * LL + c * 128)) * DD;
        for (int d = ltid; d < DD; d += 256) {
            float s = 0.f;
            #pragma unroll 4
            for (int l = 0; l < 128; ++l) s += base[(size_t)l * DD + d];
            g_partial[(b * 6 + c) * DD + d] = s;
        }
        return;
    }
    const float* src;
    __half* dst;
    int R, C;
    if (z <= NE + 1) {                 // W1 family: [D,H] -> [H,D]
        R = DD; C = HH;
        if (z <= NE) { src = ew1 + (size_t)(z - 1) * R * C; dst = g_W1e + (size_t)(z - 1) * R * C; }
        else         { src = sw1; dst = g_W1s; }
    } else {                           // W2 family: [H,D] -> [D,H]
        R = HH; C = DD;
        int e = z - NE - 2;
        if (e < NE) { src = ew2 + (size_t)e * R * C; dst = g_W2e + (size_t)e * R * C; }
        else        { src = sw2; dst = g_W2s; }
    }
    int nCB = C / 64;
    int bx = blockIdx.x % nCB;
    int by = blockIdx.x / nCB;
    if (by >= R / 64) return;
    __shared__ float t[64][65];
    int c0 = bx * 64, r0 = by * 64;
    int tx = threadIdx.x, ty = threadIdx.y;
    #pragma unroll
    for (int j = 0; j < 8; j++) {
        int row = ty + j * 8;
        const float* sp = src + (size_t)(r0 + row) * C + c0;
        t[row][tx]      = sp[tx];
        t[row][tx + 32] = sp[tx + 32];
    }
    __syncthreads();
    #pragma unroll
    for (int j = 0; j < 8; j++) {
        int cc = ty + j * 8;
        __half2 v = __floats2half2_rn(t[2 * tx][cc], t[2 * tx + 1][cc]);
        *reinterpret_cast<__half2*>(dst + (size_t)(c0 + cc) * R + r0 + 2 * tx) = v;
    }
}

// ---------------- gating stage B ----------------
__global__ void k_gate(const float* __restrict__ gate_w, const float* __restrict__ gate_b,
                       const float* __restrict__ time_cond, const float* __restrict__ time_w,
                       const float* __restrict__ time_b)
{
    int b = blockIdx.x, t = threadIdx.x;
    __shared__ float red[12][256];
    float acc[12];
    #pragma unroll
    for (int k = 0; k < 12; k++) acc[k] = 0.f;
    for (int d = t; d < DD; d += 256) {
        float h = g_partial[(b*6+0)*DD+d] + g_partial[(b*6+1)*DD+d];
        float w = g_partial[(b*6+2)*DD+d] + g_partial[(b*6+3)*DD+d];
        float p = g_partial[(b*6+4)*DD+d] + g_partial[(b*6+5)*DD+d];
        float full = (h + w + p) * (1.f / 768.f);
        float hp   = (h + p) * (1.f / 512.f);
        float wp   = (w + p) * (1.f / 512.f);
        #pragma unroll
        for (int e = 0; e < 4; e++)
            acc[e] += full * gate_w[d*4+e] + hp * gate_w[(DD+d)*4+e] + wp * gate_w[(2*DD+d)*4+e];
        float tc = time_cond[b * DD + d];
        float s  = tc / (1.f + expf(-tc));   // silu
        #pragma unroll
        for (int j = 0; j < 8; j++) acc[4 + j] += s * time_w[d*8 + j];
    }
    #pragma unroll
    for (int k = 0; k < 12; k++) red[k][t] = acc[k];
    __syncthreads();
    for (int s = 128; s > 0; s >>= 1) {
        if (t < s) {
            #pragma unroll
            for (int k = 0; k < 12; k++) red[k][t] += red[k][t + s];
        }
        __syncthreads();
    }
    if (t == 0) {
        float logit[4], prob[4];
        #pragma unroll
        for (int e = 0; e < 4; e++) {
            float sc = red[4 + e][0] + time_b[e];
            float sh = red[8 + e][0] + time_b[4 + e];
            logit[e] = (red[e][0] + gate_b[e]) * (1.f + sc) + sh;
        }
        float mx = fmaxf(fmaxf(logit[0], logit[1]), fmaxf(logit[2], logit[3]));
        float sum = 0.f;
        for (int e = 0; e < 4; e++) { prob[e] = expf(logit[e] - mx); sum += prob[e]; }
        for (int e = 0; e < 4; e++) prob[e] /= sum;
        int i1 = 0;
        for (int e = 1; e < 4; e++) if (prob[e] > prob[i1]) i1 = e;
        int i2 = -1;
        for (int e = 0; e < 4; e++) if (e != i1 && (i2 < 0 || prob[e] > prob[i2])) i2 = e;
        float denom = prob[i1] + prob[i2] + 1e-8f;
        #pragma unroll
        for (int e = 0; e < 4; e++) g_wbe[b * NE + e] = 0.f;
        g_wbe[b * NE + i1] = prob[i1] / denom;
        g_wbe[b * NE + i2] = prob[i2] / denom;
    }
}

// ---------------- GEMM1: 2 N-tiles per CTA, continuous 32-chunk pipeline ----------------
// H[z] = w * gelu(X @ W1[z] + b1[z]);  z = 0 shared, 1..4 experts
__global__ void __launch_bounds__(256, 2) k_mma1(
    const float* __restrict__ b_sh, const float* __restrict__ b_ex)
{
    constexpr int NCHT = DD / KCH;      // 16 chunks per tile
    constexpr int NT = 2;               // tiles per CTA
    constexpr int nch = NCHT * NT;      // 32 chunks total

    int bm = blockIdx.x, bn0 = blockIdx.y * NT, z = blockIdx.z;
    float w = tile_weight(z - 1, bm);
    if (w == 0.f) return;

    const __half* A = g_Xh;
    const __half* B = (z == 0) ? g_W1s : (g_W1e + (size_t)(z - 1) * HH * DD);
    const float* bias = (z == 0) ? b_sh : (b_ex + (size_t)(z - 1) * HH);
    __half* hout = g_H + (size_t)z * MT * HH;

    extern __shared__ __align__(128) char smem[];
    uint32_t sbase = smem_u32(smem);
    int tid = threadIdx.x, lane = tid & 31, wid = tid >> 5;
    int wm = wid & 3, wn = wid >> 2;
    int m0 = bm * 128;

    auto issue = [&](int flat, int slot) {
        int tile  = flat >> 4;          // 0..1
        int chunk = flat & (NCHT - 1);
        int koff = chunk * KCH;
        int n0 = (bn0 + tile) * 128;
        const __half* Ab = A + koff;
        const __half* Bb = B + koff;
        char* st = smem + slot * STG_BYTES;
        #pragma unroll
        for (int i = 0; i < 4; i++) {
            int idx = tid + i * 256;
            int r = idx >> 3, c8 = idx & 7;
            uint32_t off = (uint32_t)(r * 128 + c8 * 16);
            off ^= (off >> 3) & 0x70;
            cp_async16(st + off, Ab + (size_t)(m0 + r) * DD + c8 * 8);
        }
        #pragma unroll
        for (int i = 0; i < 4; i++) {
            int idx = tid + i * 256;
            int r = idx >> 3, c8 = idx & 7;
            uint32_t off = (uint32_t)(r * 128 + c8 * 16);
            off ^= (off >> 3) & 0x70;
            cp_async16(st + TILE_BYTES + off, Bb + (size_t)(n0 + r) * DD + c8 * 8);
        }
        cp_commit();
    };

    float c[2][8][4];
    #pragma unroll
    for (int i = 0; i < 2; i++)
        #pragma unroll
        for (int j = 0; j < 8; j++)
            #pragma unroll
            for (int q = 0; q < 4; q++) c[i][j][q] = 0.f;

    int gid = lane >> 2, tig = lane & 3;
    auto epilogue = [&](int tile) {
        int n0 = (bn0 + tile) * 128;
        #pragma unroll
        for (int i = 0; i < 2; i++) {
            int r0i = m0 + wm * 32 + i * 16 + gid;
            #pragma unroll
            for (int j = 0; j < 8; j++) {
                int col = n0 + wn * 64 + j * 8 + tig * 2;
                float b0 = __ldg(bias + col);
                float b1 = __ldg(bias + col + 1);
                __half2 h0 = __floats2half2_rn(w * gelu_t(c[i][j][0] + b0),
                                               w * gelu_t(c[i][j][1] + b1));
                __half2 h1 = __floats2half2_rn(w * gelu_t(c[i][j][2] + b0),
                                               w * gelu_t(c[i][j][3] + b1));
                *reinterpret_cast<__half2*>(hout + (size_t)r0i * HH + col) = h0;
                *reinterpret_cast<__half2*>(hout + (size_t)(r0i + 8) * HH + col) = h1;
                c[i][j][0] = c[i][j][1] = c[i][j][2] = c[i][j][3] = 0.f;   // reset for next tile
            }
        }
    };

    issue(0, 0);
    issue(1, 1);

    for (int it = 0; it < nch; ++it) {
        if (it + 1 < nch) asm volatile("cp.async.wait_group 1;" ::: "memory");
        else              asm volatile("cp.async.wait_group 0;" ::: "memory");
        __syncthreads();
        if (it + 2 < nch) issue(it + 2, (it + 2) % SS);

        uint32_t sAb = sbase + (it % SS) * STG_BYTES;
        uint32_t sBb = sAb + TILE_BYTES;
        #pragma unroll
        for (int kk = 0; kk < 4; kk++) {
            uint32_t a[2][4];
            #pragma unroll
            for (int i = 0; i < 2; i++) {
                int row = wm * 32 + i * 16 + (lane & 15);
                uint32_t off = (uint32_t)(row * 128 + kk * 32 + ((lane >> 4) & 1) * 16);
                off ^= (off >> 3) & 0x70;
                ldm4(a[i], sAb + off);
            }
            uint32_t b[8][2];
            #pragma unroll
            for (int jp = 0; jp < 4; jp++) {
                int n = wn * 64 + jp * 16 + ((lane >> 4) & 1) * 8 + (lane & 7);
                uint32_t off = (uint32_t)(n * 128 + kk * 32 + ((lane >> 3) & 1) * 16);
                off ^= (off >> 3) & 0x70;
                uint32_t r4[4];
                ldm4(r4, sBb + off);
                b[2 * jp][0] = r4[0]; b[2 * jp][1] = r4[1];
                b[2 * jp + 1][0] = r4[2]; b[2 * jp + 1][1] = r4[3];
            }
            #pragma unroll
            for (int i = 0; i < 2; i++)
                #pragma unroll
                for (int j = 0; j < 8; j++)
                    mma16816(c[i][j], a[i], b[j]);
        }
        if ((it & (NCHT - 1)) == NCHT - 1)
            epilogue(it >> 4);          // mid-stream epilogue; loads for next tile already in flight
    }
}

// ---------------- GEMM2: split-K(3) x segment-concat. P[zk] = sum over segs, K-range zk ----------------
__global__ void __launch_bounds__(256, 2) k_mma2()
{
    int bm = blockIdx.x, bn = blockIdx.y, zk = blockIdx.z;   // zk in {0,1,2}
    __shared__ const __half* sA[1 + NE];
    __shared__ const __half* sB[1 + NE];
    __shared__ int sNs;

    if (threadIdx.x == 0) {
        int ns = 0;
        sA[ns] = g_H; sB[ns] = g_W2s; ns++;
        for (int e = 0; e < NE; e++) {
            if (tile_weight(e, bm) > 0.f) {
                sA[ns] = g_H + (size_t)(e + 1) * MT * HH;
                sB[ns] = g_W2e + (size_t)e * DD * HH;
                ns++;
            }
        }
        sNs = ns;
    }
    __syncthreads();
    int ns = sNs;
    int cBeg = (zk * 64) / KSPLIT;           // chunk range within each segment
    int cCnt = ((zk + 1) * 64) / KSPLIT - cBeg;
    int nch = ns * cCnt;

    extern __shared__ __align__(128) char smem[];
    uint32_t sbase = smem_u32(smem);
    int tid = threadIdx.x, lane = tid & 31, wid = tid >> 5;
    int wm = wid & 3, wn = wid >> 2;
    int m0 = bm * 128, n0 = bn * 128;
    float* pout = g_P + (size_t)zk * MT * DD;

    auto issue = [&](int flat, int slot) {
        int seg = flat / cCnt;
        int koff = (cBeg + flat % cCnt) * KCH;
        const __half* Ab = sA[seg] + koff;
        const __half* Bb = sB[seg] + koff;
        char* st = smem + slot * STG_BYTES;
        #pragma unroll
        for (int i = 0; i < 4; i++) {
            int idx = tid + i * 256;
            int r = idx >> 3, c8 = idx & 7;
            uint32_t off = (uint32_t)(r * 128 + c8 * 16);
            off ^= (off >> 3) & 0x70;
            cp_async16(st + off, Ab + (size_t)(m0 + r) * HH + c8 * 8);
        }
        #pragma unroll
        for (int i = 0; i < 4; i++) {
            int idx = tid + i * 256;
            int r = idx >> 3, c8 = idx & 7;
            uint32_t off = (uint32_t)(r * 128 + c8 * 16);
            off ^= (off >> 3) & 0x70;
            cp_async16(st + TILE_BYTES + off, Bb + (size_t)(n0 + r) * HH + c8 * 8);
        }
        cp_commit();
    };

    float c[2][8][4];
    #pragma unroll
    for (int i = 0; i < 2; i++)
        #pragma unroll
        for (int j = 0; j < 8; j++)
            #pragma unroll
            for (int q = 0; q < 4; q++) c[i][j][q] = 0.f;

    issue(0, 0);
    issue(1, 1);

    for (int it = 0; it < nch; ++it) {
        if (it + 1 < nch) asm volatile("cp.async.wait_group 1;" ::: "memory");
        else              asm volatile("cp.async.wait_group 0;" ::: "memory");
        __syncthreads();
        if (it + 2 < nch) issue(it + 2, (it + 2) % SS);

        uint32_t sAb = sbase + (it % SS) * STG_BYTES;
        uint32_t sBb = sAb + TILE_BYTES;
        #pragma unroll
        for (int kk = 0; kk < 4; kk++) {
            uint32_t a[2][4];
            #pragma unroll
            for (int i = 0; i < 2; i++) {
                int row = wm * 32 + i * 16 + (lane & 15);
                uint32_t off = (uint32_t)(row * 128 + kk * 32 + ((lane >> 4) & 1) * 16);
                off ^= (off >> 3) & 0x70;
                ldm4(a[i], sAb + off);
            }
            uint32_t b[8][2];
            #pragma unroll
            for (int jp = 0; jp < 4; jp++) {
                int n = wn * 64 + jp * 16 + ((lane >> 4) & 1) * 8 + (lane & 7);
                uint32_t off = (uint32_t)(n * 128 + kk * 32 + ((lane >> 3) & 1) * 16);
                off ^= (off >> 3) & 0x70;
                uint32_t r4[4];
                ldm4(r4, sBb + off);
                b[2 * jp][0] = r4[0]; b[2 * jp][1] = r4[1];
                b[2 * jp + 1][0] = r4[2]; b[2 * jp + 1][1] = r4[3];
            }
            #pragma unroll
            for (int i = 0; i < 2; i++)
                #pragma unroll
                for (int j = 0; j < 8; j++)
                    mma16816(c[i][j], a[i], b[j]);
        }
    }

    int gid = lane >> 2, tig = lane & 3;
    #pragma unroll
    for (int i = 0; i < 2; i++) {
        int r0i = m0 + wm * 32 + i * 16 + gid;
        #pragma unroll
        for (int j = 0; j < 8; j++) {
            int col = n0 + wn * 64 + j * 8 + tig * 2;
            *reinterpret_cast<float2*>(pout + (size_t)r0i * DD + col) =
                make_float2(c[i][j][0], c[i][j][1]);
            *reinterpret_cast<float2*>(pout + (size_t)(r0i + 8) * DD + col) =
                make_float2(c[i][j][2], c[i][j][3]);
        }
    }
}

// ---------------- reduce: out = P0 + P1 + P2 + b_sh + sum_e w*mask*b2_e ----------------
__global__ void k_reduce(const float* __restrict__ b_sh, const float* __restrict__ b_ex,
                         float* __restrict__ out)
{
    int bm = blockIdx.x;
    int bn = blockIdx.y;
    float we[NE];
    #pragma unroll
    for (int e = 0; e < NE; e++) we[e] = tile_weight(e, bm);

    int tid = threadIdx.x;
    size_t base = (size_t)bm * 128 * DD + bn * 128;
    for (int q = tid; q < 4096; q += 256) {
        int r = q >> 5;
        int c4 = (q & 31) << 2;
        size_t off = base + (size_t)r * DD + c4;
        int col = bn * 128 + c4;
        float4 acc = *reinterpret_cast<const float4*>(g_P + off);
        float4 p1  = *reinterpret_cast<const float4*>(g_P + (size_t)MT * DD + off);
        float4 p2  = *reinterpret_cast<const float4*>(g_P + (size_t)2 * MT * DD + off);
        float4 bs  = *reinterpret_cast<const float4*>(b_sh + col);
        acc.x += p1.x + p2.x + bs.x; acc.y += p1.y + p2.y + bs.y;
        acc.z += p1.z + p2.z + bs.z; acc.w += p1.w + p2.w + bs.w;
        #pragma unroll
        for (int e = 0; e < NE; e++) {
            if (we[e] > 0.f) {
                float4 be = *reinterpret_cast<const float4*>(b_ex + (size_t)e * DD + col);
                acc.x += we[e] * be.x; acc.y += we[e] * be.y;
                acc.z += we[e] * be.z; acc.w += we[e] * be.w;
            }
        }
        *reinterpret_cast<float4*>(out + off) = acc;
    }
}

// ---------------- launch ----------------
extern "C" void kernel_launch(void* const* d_in, const int* in_sizes, int n_in,
                              void* d_out, int out_size)
{
    (void)in_sizes; (void)n_in; (void)out_size;
    const float* x         = (const float*)d_in[0];
    const float* time_cond = (const float*)d_in[1];
    const float* gate_w    = (const float*)d_in[2];
    const float* gate_b    = (const float*)d_in[3];
    const float* time_w    = (const float*)d_in[4];
    const float* time_b    = (const float*)d_in[5];
    const float* ew1       = (const float*)d_in[6];
    const float* eb1       = (const float*)d_in[7];
    const float* ew2       = (const float*)d_in[8];
    const float* eb2       = (const float*)d_in[9];
    const float* sw1       = (const float*)d_in[10];
    const float* sb1       = (const float*)d_in[11];
    const float* sw2       = (const float*)d_in[12];
    const float* sb2       = (const float*)d_in[13];
    float* out = (float*)d_out;

    cudaFuncSetAttribute(k_mma1, cudaFuncAttributeMaxDynamicSharedMemorySize, GEMM_SMEM);
    cudaFuncSetAttribute(k_mma2, cudaFuncAttributeMaxDynamicSharedMemorySize, GEMM_SMEM);

    // 1) conversions + gating stage A, one launch
    k_conv<<<dim3(1024, 1, 2 * NE + 4), dim3(32, 8)>>>(x, ew1, sw1, ew2, sw2);
    // 2) gating stage B
    k_gate<<<8, 256>>>(gate_w, gate_b, time_cond, time_w, time_b);
    // 3) GEMM1: 2 N-tiles per CTA; shared + 4 experts; inactive tiles exit
    k_mma1<<<dim3(MT / 128, HH / 256, 5), 256, GEMM_SMEM>>>(sb1, eb1);
    // 4) GEMM2: split-K(3) with in-CTA segment concat -> 3 fp32 partials
    k_mma2<<<dim3(MT / 128, DD / 128, KSPLIT), 256, GEMM_SMEM>>>();
    // 5) combine partials + biases into out (single deterministic write)
    k_reduce<<<dim3(MT / 128, DD / 128), 256>>>(sb2, eb2, out);
}

// round 13
// speedup vs baseline: 1.0232x; 1.0232x over previous
#include <cuda_runtime.h>
#include <cuda_fp16.h>
#include <cstdint>

#define DD 1024
#define HH 4096
#define NB 8
#define LL 768
#define MT 6144   // NB*LL
#define NE 4

#define KCH 64               // K halfs per chunk (128B rows)
#define SS 3                 // pipeline stages
#define TILE_BYTES 16384     // 128 rows x 128B
#define STG_BYTES 32768      // A tile + B tile
#define GEMM_SMEM (SS * STG_BYTES)   // 96 KB -> 2 CTAs/SM
#define KSPLIT 2             // GEMM2 split-K ways

// ---------------- scratch (device globals; no allocation) ----------------
__device__ __align__(256) __half g_Xh[(size_t)MT * DD];
__device__ __align__(256) __half g_W1e[(size_t)NE * HH * DD];  // W1^T per expert: [H][D]
__device__ __align__(256) __half g_W2e[(size_t)NE * DD * HH];  // W2^T per expert: [D][H]
__device__ __align__(256) __half g_W1s[(size_t)HH * DD];       // sw1^T
__device__ __align__(256) __half g_W2s[(size_t)DD * HH];       // sw2^T
__device__ __align__(256) __half g_H[(size_t)5 * MT * HH];     // [shared, e0..e3] hidden
__device__ __align__(256) float  g_P[(size_t)KSPLIT * MT * DD]; // GEMM2 split-K partials
__device__ float  g_partial[NB * 6 * DD];
__device__ float  g_wbe[NB * NE];

// ---------------- helpers ----------------
__device__ __forceinline__ uint32_t smem_u32(const void* p) {
    uint32_t a;
    asm("{ .reg .u64 t; cvta.to.shared.u64 t, %1; cvt.u32.u64 %0, t; }" : "=r"(a) : "l"(p));
    return a;
}
__device__ __forceinline__ void cp_async16(void* smem, const void* gmem) {
    unsigned s = (unsigned)__cvta_generic_to_shared(smem);
    asm volatile("cp.async.cg.shared.global [%0], [%1], 16;\n" :: "r"(s), "l"(gmem) : "memory");
}
__device__ __forceinline__ void cp_commit() { asm volatile("cp.async.commit_group;\n" ::: "memory"); }

__device__ __forceinline__ void ldm4(uint32_t* r, uint32_t addr) {
    asm volatile("ldmatrix.sync.aligned.m8n8.x4.shared.b16 {%0,%1,%2,%3}, [%4];"
        : "=r"(r[0]), "=r"(r[1]), "=r"(r[2]), "=r"(r[3]) : "r"(addr));
}
__device__ __forceinline__ void mma16816(float* c, const uint32_t* a, const uint32_t* b) {
    asm volatile(
        "mma.sync.aligned.m16n8k16.row.col.f32.f16.f16.f32 "
        "{%0,%1,%2,%3}, {%4,%5,%6,%7}, {%8,%9}, {%0,%1,%2,%3};"
        : "+f"(c[0]), "+f"(c[1]), "+f"(c[2]), "+f"(c[3])
        : "r"(a[0]), "r"(a[1]), "r"(a[2]), "r"(a[3]), "r"(b[0]), "r"(b[1]));
}

// fast GELU (tanh approx via single-instruction MUFU tanh)
__device__ __forceinline__ float gelu_t(float v) {
    float c = 0.7978845608028654f * (v + 0.044715f * v * v * v);
    float t;
    asm("tanh.approx.f32 %0, %1;" : "=f"(t) : "f"(c));
    return 0.5f * v * (1.f + t);
}

// per-M-tile weight: batch gating weight x third-mask; exact 0 => skip tile
__device__ __forceinline__ float tile_weight(int expert, int bm) {
    if (expert < 0) return 1.f;
    int b = bm / 6;             // 6 tiles of 128 tokens per batch
    int third = (bm % 6) >> 1;  // 0 head, 1 wrist, 2 proprio
    if (expert == 1 && third == 1) return 0.f;
    if (expert == 2 && third == 0) return 0.f;
    return g_wbe[b * NE + expert];
}

// ---------------- merged conversion + stageA kernel ----------------
__global__ void k_conv(const float* __restrict__ x,
                       const float* __restrict__ ew1, const float* __restrict__ sw1,
                       const float* __restrict__ ew2, const float* __restrict__ sw2)
{
    int z = blockIdx.z;
    int ltid = threadIdx.y * 32 + threadIdx.x;   // 0..255
    if (z == 0) {
        int n4 = MT * DD / 4;
        int stride = gridDim.x * 256;
        for (int i = ltid + blockIdx.x * 256; i < n4; i += stride) {
            float4 v = reinterpret_cast<const float4*>(x)[i];
            __half2* d2 = reinterpret_cast<__half2*>(g_Xh) + (size_t)i * 2;
            d2[0] = __floats2half2_rn(v.x, v.y);
            d2[1] = __floats2half2_rn(v.z, v.w);
        }
        return;
    }
    if (z == 2 * NE + 3) {
        if (blockIdx.x >= NB * 6) return;
        int b = blockIdx.x / 6, c = blockIdx.x % 6;
        const float* base = x + ((size_t)(b * LL + c * 128)) * DD;
        for (int d = ltid; d < DD; d += 256) {
            float s = 0.f;
            #pragma unroll 4
            for (int l = 0; l < 128; ++l) s += base[(size_t)l * DD + d];
            g_partial[(b * 6 + c) * DD + d] = s;
        }
        return;
    }
    const float* src;
    __half* dst;
    int R, C;
    if (z <= NE + 1) {                 // W1 family: [D,H] -> [H,D]
        R = DD; C = HH;
        if (z <= NE) { src = ew1 + (size_t)(z - 1) * R * C; dst = g_W1e + (size_t)(z - 1) * R * C; }
        else         { src = sw1; dst = g_W1s; }
    } else {                           // W2 family: [H,D] -> [D,H]
        R = HH; C = DD;
        int e = z - NE - 2;
        if (e < NE) { src = ew2 + (size_t)e * R * C; dst = g_W2e + (size_t)e * R * C; }
        else        { src = sw2; dst = g_W2s; }
    }
    int nCB = C / 64;
    int bx = blockIdx.x % nCB;
    int by = blockIdx.x / nCB;
    if (by >= R / 64) return;
    __shared__ float t[64][65];
    int c0 = bx * 64, r0 = by * 64;
    int tx = threadIdx.x, ty = threadIdx.y;
    #pragma unroll
    for (int j = 0; j < 8; j++) {
        int row = ty + j * 8;
        const float* sp = src + (size_t)(r0 + row) * C + c0;
        t[row][tx]      = sp[tx];
        t[row][tx + 32] = sp[tx + 32];
    }
    __syncthreads();
    #pragma unroll
    for (int j = 0; j < 8; j++) {
        int cc = ty + j * 8;
        __half2 v = __floats2half2_rn(t[2 * tx][cc], t[2 * tx + 1][cc]);
        *reinterpret_cast<__half2*>(dst + (size_t)(c0 + cc) * R + r0 + 2 * tx) = v;
    }
}

// ---------------- gating stage B ----------------
__global__ void k_gate(const float* __restrict__ gate_w, const float* __restrict__ gate_b,
                       const float* __restrict__ time_cond, const float* __restrict__ time_w,
                       const float* __restrict__ time_b)
{
    int b = blockIdx.x, t = threadIdx.x;
    __shared__ float red[12][256];
    float acc[12];
    #pragma unroll
    for (int k = 0; k < 12; k++) acc[k] = 0.f;
    for (int d = t; d < DD; d += 256) {
        float h = g_partial[(b*6+0)*DD+d] + g_partial[(b*6+1)*DD+d];
        float w = g_partial[(b*6+2)*DD+d] + g_partial[(b*6+3)*DD+d];
        float p = g_partial[(b*6+4)*DD+d] + g_partial[(b*6+5)*DD+d];
        float full = (h + w + p) * (1.f / 768.f);
        float hp   = (h + p) * (1.f / 512.f);
        float wp   = (w + p) * (1.f / 512.f);
        #pragma unroll
        for (int e = 0; e < 4; e++)
            acc[e] += full * gate_w[d*4+e] + hp * gate_w[(DD+d)*4+e] + wp * gate_w[(2*DD+d)*4+e];
        float tc = time_cond[b * DD + d];
        float s  = tc / (1.f + expf(-tc));   // silu
        #pragma unroll
        for (int j = 0; j < 8; j++) acc[4 + j] += s * time_w[d*8 + j];
    }
    #pragma unroll
    for (int k = 0; k < 12; k++) red[k][t] = acc[k];
    __syncthreads();
    for (int s = 128; s > 0; s >>= 1) {
        if (t < s) {
            #pragma unroll
            for (int k = 0; k < 12; k++) red[k][t] += red[k][t + s];
        }
        __syncthreads();
    }
    if (t == 0) {
        float logit[4], prob[4];
        #pragma unroll
        for (int e = 0; e < 4; e++) {
            float sc = red[4 + e][0] + time_b[e];
            float sh = red[8 + e][0] + time_b[4 + e];
            logit[e] = (red[e][0] + gate_b[e]) * (1.f + sc) + sh;
        }
        float mx = fmaxf(fmaxf(logit[0], logit[1]), fmaxf(logit[2], logit[3]));
        float sum = 0.f;
        for (int e = 0; e < 4; e++) { prob[e] = expf(logit[e] - mx); sum += prob[e]; }
        for (int e = 0; e < 4; e++) prob[e] /= sum;
        int i1 = 0;
        for (int e = 1; e < 4; e++) if (prob[e] > prob[i1]) i1 = e;
        int i2 = -1;
        for (int e = 0; e < 4; e++) if (e != i1 && (i2 < 0 || prob[e] > prob[i2])) i2 = e;
        float denom = prob[i1] + prob[i2] + 1e-8f;
        #pragma unroll
        for (int e = 0; e < 4; e++) g_wbe[b * NE + e] = 0.f;
        g_wbe[b * NE + i1] = prob[i1] / denom;
        g_wbe[b * NE + i2] = prob[i2] / denom;
    }
}

// ---------------- GEMM1: 4 N-tiles per CTA, continuous 64-chunk pipeline ----------------
// H[z] = w * gelu(X @ W1[z] + b1[z]);  z = 0 shared, 1..4 experts
__global__ void __launch_bounds__(256, 2) k_mma1(
    const float* __restrict__ b_sh, const float* __restrict__ b_ex)
{
    constexpr int NCHT = DD / KCH;      // 16 chunks per tile
    constexpr int NT = 4;               // tiles per CTA
    constexpr int nch = NCHT * NT;      // 64 chunks total

    int bm = blockIdx.x, bn0 = blockIdx.y * NT, z = blockIdx.z;
    float w = tile_weight(z - 1, bm);
    if (w == 0.f) return;

    const __half* A = g_Xh;
    const __half* B = (z == 0) ? g_W1s : (g_W1e + (size_t)(z - 1) * HH * DD);
    const float* bias = (z == 0) ? b_sh : (b_ex + (size_t)(z - 1) * HH);
    __half* hout = g_H + (size_t)z * MT * HH;

    extern __shared__ __align__(128) char smem[];
    uint32_t sbase = smem_u32(smem);
    int tid = threadIdx.x, lane = tid & 31, wid = tid >> 5;
    int wm = wid & 3, wn = wid >> 2;
    int m0 = bm * 128;

    auto issue = [&](int flat, int slot) {
        int tile  = flat >> 4;          // 0..3
        int chunk = flat & (NCHT - 1);
        int koff = chunk * KCH;
        int n0 = (bn0 + tile) * 128;
        const __half* Ab = A + koff;
        const __half* Bb = B + koff;
        char* st = smem + slot * STG_BYTES;
        #pragma unroll
        for (int i = 0; i < 4; i++) {
            int idx = tid + i * 256;
            int r = idx >> 3, c8 = idx & 7;
            uint32_t off = (uint32_t)(r * 128 + c8 * 16);
            off ^= (off >> 3) & 0x70;
            cp_async16(st + off, Ab + (size_t)(m0 + r) * DD + c8 * 8);
        }
        #pragma unroll
        for (int i = 0; i < 4; i++) {
            int idx = tid + i * 256;
            int r = idx >> 3, c8 = idx & 7;
            uint32_t off = (uint32_t)(r * 128 + c8 * 16);
            off ^= (off >> 3) & 0x70;
            cp_async16(st + TILE_BYTES + off, Bb + (size_t)(n0 + r) * DD + c8 * 8);
        }
        cp_commit();
    };

    float c[2][8][4];
    #pragma unroll
    for (int i = 0; i < 2; i++)
        #pragma unroll
        for (int j = 0; j < 8; j++)
            #pragma unroll
            for (int q = 0; q < 4; q++) c[i][j][q] = 0.f;

    int gid = lane >> 2, tig = lane & 3;
    auto epilogue = [&](int tile) {
        int n0 = (bn0 + tile) * 128;
        #pragma unroll
        for (int i = 0; i < 2; i++) {
            int r0i = m0 + wm * 32 + i * 16 + gid;
            #pragma unroll
            for (int j = 0; j < 8; j++) {
                int col = n0 + wn * 64 + j * 8 + tig * 2;
                float b0 = __ldg(bias + col);
                float b1 = __ldg(bias + col + 1);
                __half2 h0 = __floats2half2_rn(w * gelu_t(c[i][j][0] + b0),
                                               w * gelu_t(c[i][j][1] + b1));
                __half2 h1 = __floats2half2_rn(w * gelu_t(c[i][j][2] + b0),
                                               w * gelu_t(c[i][j][3] + b1));
                *reinterpret_cast<__half2*>(hout + (size_t)r0i * HH + col) = h0;
                *reinterpret_cast<__half2*>(hout + (size_t)(r0i + 8) * HH + col) = h1;
                c[i][j][0] = c[i][j][1] = c[i][j][2] = c[i][j][3] = 0.f;   // reset for next tile
            }
        }
    };

    issue(0, 0);
    issue(1, 1);

    for (int it = 0; it < nch; ++it) {
        if (it + 1 < nch) asm volatile("cp.async.wait_group 1;" ::: "memory");
        else              asm volatile("cp.async.wait_group 0;" ::: "memory");
        __syncthreads();
        if (it + 2 < nch) issue(it + 2, (it + 2) % SS);

        uint32_t sAb = sbase + (it % SS) * STG_BYTES;
        uint32_t sBb = sAb + TILE_BYTES;
        #pragma unroll
        for (int kk = 0; kk < 4; kk++) {
            uint32_t a[2][4];
            #pragma unroll
            for (int i = 0; i < 2; i++) {
                int row = wm * 32 + i * 16 + (lane & 15);
                uint32_t off = (uint32_t)(row * 128 + kk * 32 + ((lane >> 4) & 1) * 16);
                off ^= (off >> 3) & 0x70;
                ldm4(a[i], sAb + off);
            }
            uint32_t b[8][2];
            #pragma unroll
            for (int jp = 0; jp < 4; jp++) {
                int n = wn * 64 + jp * 16 + ((lane >> 4) & 1) * 8 + (lane & 7);
                uint32_t off = (uint32_t)(n * 128 + kk * 32 + ((lane >> 3) & 1) * 16);
                off ^= (off >> 3) & 0x70;
                uint32_t r4[4];
                ldm4(r4, sBb + off);
                b[2 * jp][0] = r4[0]; b[2 * jp][1] = r4[1];
                b[2 * jp + 1][0] = r4[2]; b[2 * jp + 1][1] = r4[3];
            }
            #pragma unroll
            for (int i = 0; i < 2; i++)
                #pragma unroll
                for (int j = 0; j < 8; j++)
                    mma16816(c[i][j], a[i], b[j]);
        }
        if ((it & (NCHT - 1)) == NCHT - 1)
            epilogue(it >> 4);          // mid-stream epilogue; loads for next tile already in flight
    }
}

// ---------------- GEMM2: split-K(2) x segment-concat. P[zk] = sum over segs, K-half zk ----------------
__global__ void __launch_bounds__(256, 2) k_mma2()
{
    int bm = blockIdx.x, bn = blockIdx.y, zk = blockIdx.z;   // zk in {0,1}
    __shared__ const __half* sA[1 + NE];
    __shared__ const __half* sB[1 + NE];
    __shared__ int sNs;

    if (threadIdx.x == 0) {
        int ns = 0;
        sA[ns] = g_H; sB[ns] = g_W2s; ns++;
        for (int e = 0; e < NE; e++) {
            if (tile_weight(e, bm) > 0.f) {
                sA[ns] = g_H + (size_t)(e + 1) * MT * HH;
                sB[ns] = g_W2e + (size_t)e * DD * HH;
                ns++;
            }
        }
        sNs = ns;
    }
    __syncthreads();
    int ns = sNs;
    int nch = ns * 32;                  // 32 chunks = K-half (2048) per segment
    int kbase = zk * 2048;

    extern __shared__ __align__(128) char smem[];
    uint32_t sbase = smem_u32(smem);
    int tid = threadIdx.x, lane = tid & 31, wid = tid >> 5;
    int wm = wid & 3, wn = wid >> 2;
    int m0 = bm * 128, n0 = bn * 128;
    float* pout = g_P + (size_t)zk * MT * DD;

    auto issue = [&](int flat, int slot) {
        int seg = flat >> 5;
        int koff = kbase + (flat & 31) * KCH;
        const __half* Ab = sA[seg] + koff;
        const __half* Bb = sB[seg] + koff;
        char* st = smem + slot * STG_BYTES;
        #pragma unroll
        for (int i = 0; i < 4; i++) {
            int idx = tid + i * 256;
            int r = idx >> 3, c8 = idx & 7;
            uint32_t off = (uint32_t)(r * 128 + c8 * 16);
            off ^= (off >> 3) & 0x70;
            cp_async16(st + off, Ab + (size_t)(m0 + r) * HH + c8 * 8);
        }
        #pragma unroll
        for (int i = 0; i < 4; i++) {
            int idx = tid + i * 256;
            int r = idx >> 3, c8 = idx & 7;
            uint32_t off = (uint32_t)(r * 128 + c8 * 16);
            off ^= (off >> 3) & 0x70;
            cp_async16(st + TILE_BYTES + off, Bb + (size_t)(n0 + r) * HH + c8 * 8);
        }
        cp_commit();
    };

    float c[2][8][4];
    #pragma unroll
    for (int i = 0; i < 2; i++)
        #pragma unroll
        for (int j = 0; j < 8; j++)
            #pragma unroll
            for (int q = 0; q < 4; q++) c[i][j][q] = 0.f;

    issue(0, 0);
    issue(1, 1);

    for (int it = 0; it < nch; ++it) {
        if (it + 1 < nch) asm volatile("cp.async.wait_group 1;" ::: "memory");
        else              asm volatile("cp.async.wait_group 0;" ::: "memory");
        __syncthreads();
        if (it + 2 < nch) issue(it + 2, (it + 2) % SS);

        uint32_t sAb = sbase + (it % SS) * STG_BYTES;
        uint32_t sBb = sAb + TILE_BYTES;
        #pragma unroll
        for (int kk = 0; kk < 4; kk++) {
            uint32_t a[2][4];
            #pragma unroll
            for (int i = 0; i < 2; i++) {
                int row = wm * 32 + i * 16 + (lane & 15);
                uint32_t off = (uint32_t)(row * 128 + kk * 32 + ((lane >> 4) & 1) * 16);
                off ^= (off >> 3) & 0x70;
                ldm4(a[i], sAb + off);
            }
            uint32_t b[8][2];
            #pragma unroll
            for (int jp = 0; jp < 4; jp++) {
                int n = wn * 64 + jp * 16 + ((lane >> 4) & 1) * 8 + (lane & 7);
                uint32_t off = (uint32_t)(n * 128 + kk * 32 + ((lane >> 3) & 1) * 16);
                off ^= (off >> 3) & 0x70;
                uint32_t r4[4];
                ldm4(r4, sBb + off);
                b[2 * jp][0] = r4[0]; b[2 * jp][1] = r4[1];
                b[2 * jp + 1][0] = r4[2]; b[2 * jp + 1][1] = r4[3];
            }
            #pragma unroll
            for (int i = 0; i < 2; i++)
                #pragma unroll
                for (int j = 0; j < 8; j++)
                    mma16816(c[i][j], a[i], b[j]);
        }
    }

    int gid = lane >> 2, tig = lane & 3;
    #pragma unroll
    for (int i = 0; i < 2; i++) {
        int r0i = m0 + wm * 32 + i * 16 + gid;
        #pragma unroll
        for (int j = 0; j < 8; j++) {
            int col = n0 + wn * 64 + j * 8 + tig * 2;
            *reinterpret_cast<float2*>(pout + (size_t)r0i * DD + col) =
                make_float2(c[i][j][0], c[i][j][1]);
            *reinterpret_cast<float2*>(pout + (size_t)(r0i + 8) * DD + col) =
                make_float2(c[i][j][2], c[i][j][3]);
        }
    }
}

// ---------------- reduce: out = P0 + P1 + b_sh + sum_e w*mask*b2_e ----------------
__global__ void k_reduce(const float* __restrict__ b_sh, const float* __restrict__ b_ex,
                         float* __restrict__ out)
{
    int bm = blockIdx.x;
    int bn = blockIdx.y;
    float we[NE];
    #pragma unroll
    for (int e = 0; e < NE; e++) we[e] = tile_weight(e, bm);

    int tid = threadIdx.x;
    size_t base = (size_t)bm * 128 * DD + bn * 128;
    for (int q = tid; q < 4096; q += 256) {
        int r = q >> 5;
        int c4 = (q & 31) << 2;
        size_t off = base + (size_t)r * DD + c4;
        int col = bn * 128 + c4;
        float4 acc = *reinterpret_cast<const float4*>(g_P + off);
        float4 p1  = *reinterpret_cast<const float4*>(g_P + (size_t)MT * DD + off);
        float4 bs  = *reinterpret_cast<const float4*>(b_sh + col);
        acc.x += p1.x + bs.x; acc.y += p1.y + bs.y;
        acc.z += p1.z + bs.z; acc.w += p1.w + bs.w;
        #pragma unroll
        for (int e = 0; e < NE; e++) {
            if (we[e] > 0.f) {
                float4 be = *reinterpret_cast<const float4*>(b_ex + (size_t)e * DD + col);
                acc.x += we[e] * be.x; acc.y += we[e] * be.y;
                acc.z += we[e] * be.z; acc.w += we[e] * be.w;
            }
        }
        *reinterpret_cast<float4*>(out + off) = acc;
    }
}

// ---------------- launch ----------------
extern "C" void kernel_launch(void* const* d_in, const int* in_sizes, int n_in,
                              void* d_out, int out_size)
{
    (void)in_sizes; (void)n_in; (void)out_size;
    const float* x         = (const float*)d_in[0];
    const float* time_cond = (const float*)d_in[1];
    const float* gate_w    = (const float*)d_in[2];
    const float* gate_b    = (const float*)d_in[3];
    const float* time_w    = (const float*)d_in[4];
    const float* time_b    = (const float*)d_in[5];
    const float* ew1       = (const float*)d_in[6];
    const float* eb1       = (const float*)d_in[7];
    const float* ew2       = (const float*)d_in[8];
    const float* eb2       = (const float*)d_in[9];
    const float* sw1       = (const float*)d_in[10];
    const float* sb1       = (const float*)d_in[11];
    const float* sw2       = (const float*)d_in[12];
    const float* sb2       = (const float*)d_in[13];
    float* out = (float*)d_out;

    cudaFuncSetAttribute(k_mma1, cudaFuncAttributeMaxDynamicSharedMemorySize, GEMM_SMEM);
    cudaFuncSetAttribute(k_mma2, cudaFuncAttributeMaxDynamicSharedMemorySize, GEMM_SMEM);

    // 1) conversions + gating stage A, one launch
    k_conv<<<dim3(1024, 1, 2 * NE + 4), dim3(32, 8)>>>(x, ew1, sw1, ew2, sw2);
    // 2) gating stage B
    k_gate<<<8, 256>>>(gate_w, gate_b, time_cond, time_w, time_b);
    // 3) GEMM1: 4 N-tiles per CTA; shared + 4 experts; inactive tiles exit
    k_mma1<<<dim3(MT / 128, HH / 512, 5), 256, GEMM_SMEM>>>(sb1, eb1);
    // 4) GEMM2: split-K(2) with in-CTA segment concat -> 2 fp32 partials
    k_mma2<<<dim3(MT / 128, DD / 128, KSPLIT), 256, GEMM_SMEM>>>();
    // 5) combine partials + biases into out (single deterministic write)
    k_reduce<<<dim3(MT / 128, DD / 128), 256>>>(sb2, eb2, out);
}

// round 14
// speedup vs baseline: 1.0315x; 1.0081x over previous
#include <cuda_runtime.h>
#include <cuda_fp16.h>
#include <cstdint>

#define DD 1024
#define HH 4096
#define NB 8
#define LL 768
#define MT 6144   // NB*LL
#define NE 4

#define KCH 64               // K halfs per chunk (128B rows)
#define SS 3                 // pipeline stages
#define TILE_BYTES 16384     // 128 rows x 128B
#define STG_BYTES 32768      // A tile + B tile
#define GEMM_SMEM (SS * STG_BYTES)   // 96 KB -> 2 CTAs/SM
#define KSPLIT 2             // GEMM2 split-K ways

// ---------------- scratch (device globals; no allocation) ----------------
__device__ __align__(256) __half g_Xh[(size_t)MT * DD];
__device__ __align__(256) __half g_W1e[(size_t)NE * HH * DD];  // W1^T per expert: [H][D]
__device__ __align__(256) __half g_W2e[(size_t)NE * DD * HH];  // W2^T per expert: [D][H]
__device__ __align__(256) __half g_W1s[(size_t)HH * DD];       // sw1^T
__device__ __align__(256) __half g_W2s[(size_t)DD * HH];       // sw2^T
__device__ __align__(256) __half g_H[(size_t)5 * MT * HH];     // [shared, e0..e3] hidden
__device__ __align__(256) float  g_P[(size_t)KSPLIT * MT * DD]; // GEMM2 split-K partials
__device__ float  g_partial[NB * 6 * DD];
__device__ float  g_wbe[NB * NE];

// ---------------- helpers ----------------
__device__ __forceinline__ uint32_t smem_u32(const void* p) {
    uint32_t a;
    asm("{ .reg .u64 t; cvta.to.shared.u64 t, %1; cvt.u32.u64 %0, t; }" : "=r"(a) : "l"(p));
    return a;
}
__device__ __forceinline__ void cp_async16(void* smem, const void* gmem) {
    unsigned s = (unsigned)__cvta_generic_to_shared(smem);
    asm volatile("cp.async.cg.shared.global [%0], [%1], 16;\n" :: "r"(s), "l"(gmem) : "memory");
}
__device__ __forceinline__ void cp_commit() { asm volatile("cp.async.commit_group;\n" ::: "memory"); }

__device__ __forceinline__ void ldm4(uint32_t* r, uint32_t addr) {
    asm volatile("ldmatrix.sync.aligned.m8n8.x4.shared.b16 {%0,%1,%2,%3}, [%4];"
        : "=r"(r[0]), "=r"(r[1]), "=r"(r[2]), "=r"(r[3]) : "r"(addr));
}
__device__ __forceinline__ void mma16816(float* c, const uint32_t* a, const uint32_t* b) {
    asm volatile(
        "mma.sync.aligned.m16n8k16.row.col.f32.f16.f16.f32 "
        "{%0,%1,%2,%3}, {%4,%5,%6,%7}, {%8,%9}, {%0,%1,%2,%3};"
        : "+f"(c[0]), "+f"(c[1]), "+f"(c[2]), "+f"(c[3])
        : "r"(a[0]), "r"(a[1]), "r"(a[2]), "r"(a[3]), "r"(b[0]), "r"(b[1]));
}

// fast GELU (tanh approx via single-instruction MUFU tanh)
__device__ __forceinline__ float gelu_t(float v) {
    float c = 0.7978845608028654f * (v + 0.044715f * v * v * v);
    float t;
    asm("tanh.approx.f32 %0, %1;" : "=f"(t) : "f"(c));
    return 0.5f * v * (1.f + t);
}

// per-M-tile weight: batch gating weight x third-mask; exact 0 => skip tile
__device__ __forceinline__ float tile_weight(int expert, int bm) {
    if (expert < 0) return 1.f;
    int b = bm / 6;             // 6 tiles of 128 tokens per batch
    int third = (bm % 6) >> 1;  // 0 head, 1 wrist, 2 proprio
    if (expert == 1 && third == 1) return 0.f;
    if (expert == 2 && third == 0) return 0.f;
    return g_wbe[b * NE + expert];
}

// ---------------- merged conversion + stageA kernel ----------------
// z == 0          : x fp32 -> fp16 into g_Xh
// z in 1..NE      : ew1 expert [D,H] -> [H,D]
// z == NE+1       : sw1 -> g_W1s
// z in NE+2..2NE+1: ew2 expert [H,D] -> [D,H]
// z == 2NE+2      : sw2 -> g_W2s
// z == 2NE+3      : gating stage A partial sums (blocks 0..47)
__global__ void k_conv(const float* __restrict__ x,
                       const float* __restrict__ ew1, const float* __restrict__ sw1,
                       const float* __restrict__ ew2, const float* __restrict__ sw2)
{
    int z = blockIdx.z;
    int ltid = threadIdx.y * 32 + threadIdx.x;   // 0..255
    if (z == 0) {
        int n4 = MT * DD / 4;
        int stride = gridDim.x * 256;
        for (int i = ltid + blockIdx.x * 256; i < n4; i += stride) {
            float4 v = reinterpret_cast<const float4*>(x)[i];
            __half2* d2 = reinterpret_cast<__half2*>(g_Xh) + (size_t)i * 2;
            d2[0] = __floats2half2_rn(v.x, v.y);
            d2[1] = __floats2half2_rn(v.z, v.w);
        }
        return;
    }
    if (z == 2 * NE + 3) {
        if (blockIdx.x >= NB * 6) return;
        int b = blockIdx.x / 6, c = blockIdx.x % 6;
        const float* base = x + ((size_t)(b * LL + c * 128)) * DD;
        for (int d = ltid; d < DD; d += 256) {
            float s = 0.f;
            #pragma unroll 4
            for (int l = 0; l < 128; ++l) s += base[(size_t)l * DD + d];
            g_partial[(b * 6 + c) * DD + d] = s;
        }
        return;
    }
    const float* src;
    __half* dst;
    int R, C;
    if (z <= NE + 1) {                 // W1 family: [D,H] -> [H,D]
        R = DD; C = HH;
        if (z <= NE) { src = ew1 + (size_t)(z - 1) * R * C; dst = g_W1e + (size_t)(z - 1) * R * C; }
        else         { src = sw1; dst = g_W1s; }
    } else {                           // W2 family: [H,D] -> [D,H]
        R = HH; C = DD;
        int e = z - NE - 2;
        if (e < NE) { src = ew2 + (size_t)e * R * C; dst = g_W2e + (size_t)e * R * C; }
        else        { src = sw2; dst = g_W2s; }
    }
    int nCB = C / 64;
    int bx = blockIdx.x % nCB;
    int by = blockIdx.x / nCB;
    if (by >= R / 64) return;
    __shared__ float t[64][65];
    int c0 = bx * 64, r0 = by * 64;
    int tx = threadIdx.x, ty = threadIdx.y;
    #pragma unroll
    for (int j = 0; j < 8; j++) {
        int row = ty + j * 8;
        const float2* sp = reinterpret_cast<const float2*>(src + (size_t)(r0 + row) * C + c0);
        float2 v = sp[tx];              // cols 2tx, 2tx+1  (LDG.64, warp = 256B)
        t[row][2 * tx]     = v.x;
        t[row][2 * tx + 1] = v.y;
    }
    __syncthreads();
    #pragma unroll
    for (int j = 0; j < 8; j++) {
        int cc = ty + j * 8;
        __half2 v = __floats2half2_rn(t[2 * tx][cc], t[2 * tx + 1][cc]);
        *reinterpret_cast<__half2*>(dst + (size_t)(c0 + cc) * R + r0 + 2 * tx) = v;
    }
}

// ---------------- gating stage B ----------------
__global__ void k_gate(const float* __restrict__ gate_w, const float* __restrict__ gate_b,
                       const float* __restrict__ time_cond, const float* __restrict__ time_w,
                       const float* __restrict__ time_b)
{
    int b = blockIdx.x, t = threadIdx.x;
    __shared__ float red[12][256];
    float acc[12];
    #pragma unroll
    for (int k = 0; k < 12; k++) acc[k] = 0.f;
    for (int d = t; d < DD; d += 256) {
        float h = g_partial[(b*6+0)*DD+d] + g_partial[(b*6+1)*DD+d];
        float w = g_partial[(b*6+2)*DD+d] + g_partial[(b*6+3)*DD+d];
        float p = g_partial[(b*6+4)*DD+d] + g_partial[(b*6+5)*DD+d];
        float full = (h + w + p) * (1.f / 768.f);
        float hp   = (h + p) * (1.f / 512.f);
        float wp   = (w + p) * (1.f / 512.f);
        #pragma unroll
        for (int e = 0; e < 4; e++)
            acc[e] += full * gate_w[d*4+e] + hp * gate_w[(DD+d)*4+e] + wp * gate_w[(2*DD+d)*4+e];
        float tc = time_cond[b * DD + d];
        float s  = tc / (1.f + expf(-tc));   // silu
        #pragma unroll
        for (int j = 0; j < 8; j++) acc[4 + j] += s * time_w[d*8 + j];
    }
    #pragma unroll
    for (int k = 0; k < 12; k++) red[k][t] = acc[k];
    __syncthreads();
    for (int s = 128; s > 0; s >>= 1) {
        if (t < s) {
            #pragma unroll
            for (int k = 0; k < 12; k++) red[k][t] += red[k][t + s];
        }
        __syncthreads();
    }
    if (t == 0) {
        float logit[4], prob[4];
        #pragma unroll
        for (int e = 0; e < 4; e++) {
            float sc = red[4 + e][0] + time_b[e];
            float sh = red[8 + e][0] + time_b[4 + e];
            logit[e] = (red[e][0] + gate_b[e]) * (1.f + sc) + sh;
        }
        float mx = fmaxf(fmaxf(logit[0], logit[1]), fmaxf(logit[2], logit[3]));
        float sum = 0.f;
        for (int e = 0; e < 4; e++) { prob[e] = expf(logit[e] - mx); sum += prob[e]; }
        for (int e = 0; e < 4; e++) prob[e] /= sum;
        int i1 = 0;
        for (int e = 1; e < 4; e++) if (prob[e] > prob[i1]) i1 = e;
        int i2 = -1;
        for (int e = 0; e < 4; e++) if (e != i1 && (i2 < 0 || prob[e] > prob[i2])) i2 = e;
        float denom = prob[i1] + prob[i2] + 1e-8f;
        #pragma unroll
        for (int e = 0; e < 4; e++) g_wbe[b * NE + e] = 0.f;
        g_wbe[b * NE + i1] = prob[i1] / denom;
        g_wbe[b * NE + i2] = prob[i2] / denom;
    }
}

// ---------------- GEMM1: 2 N-tiles per CTA, continuous 32-chunk pipeline ----------------
// H[z] = w * gelu(X @ W1[z] + b1[z]);  z = 0 shared, 1..4 experts
__global__ void __launch_bounds__(256, 2) k_mma1(
    const float* __restrict__ b_sh, const float* __restrict__ b_ex)
{
    constexpr int NCHT = DD / KCH;      // 16 chunks per tile
    constexpr int NT = 2;               // tiles per CTA
    constexpr int nch = NCHT * NT;      // 32 chunks total

    int bm = blockIdx.x, bn0 = blockIdx.y * NT, z = blockIdx.z;
    float w = tile_weight(z - 1, bm);
    if (w == 0.f) return;

    const __half* A = g_Xh;
    const __half* B = (z == 0) ? g_W1s : (g_W1e + (size_t)(z - 1) * HH * DD);
    const float* bias = (z == 0) ? b_sh : (b_ex + (size_t)(z - 1) * HH);
    __half* hout = g_H + (size_t)z * MT * HH;

    extern __shared__ __align__(128) char smem[];
    uint32_t sbase = smem_u32(smem);
    int tid = threadIdx.x, lane = tid & 31, wid = tid >> 5;
    int wm = wid & 3, wn = wid >> 2;
    int m0 = bm * 128;

    auto issue = [&](int flat, int slot) {
        int tile  = flat >> 4;          // 0..1
        int chunk = flat & (NCHT - 1);
        int koff = chunk * KCH;
        int n0 = (bn0 + tile) * 128;
        const __half* Ab = A + koff;
        const __half* Bb = B + koff;
        char* st = smem + slot * STG_BYTES;
        #pragma unroll
        for (int i = 0; i < 4; i++) {
            int idx = tid + i * 256;
            int r = idx >> 3, c8 = idx & 7;
            uint32_t off = (uint32_t)(r * 128 + c8 * 16);
            off ^= (off >> 3) & 0x70;
            cp_async16(st + off, Ab + (size_t)(m0 + r) * DD + c8 * 8);
        }
        #pragma unroll
        for (int i = 0; i < 4; i++) {
            int idx = tid + i * 256;
            int r = idx >> 3, c8 = idx & 7;
            uint32_t off = (uint32_t)(r * 128 + c8 * 16);
            off ^= (off >> 3) & 0x70;
            cp_async16(st + TILE_BYTES + off, Bb + (size_t)(n0 + r) * DD + c8 * 8);
        }
        cp_commit();
    };

    float c[2][8][4];
    #pragma unroll
    for (int i = 0; i < 2; i++)
        #pragma unroll
        for (int j = 0; j < 8; j++)
            #pragma unroll
            for (int q = 0; q < 4; q++) c[i][j][q] = 0.f;

    int gid = lane >> 2, tig = lane & 3;
    auto epilogue = [&](int tile) {
        int n0 = (bn0 + tile) * 128;
        #pragma unroll
        for (int i = 0; i < 2; i++) {
            int r0i = m0 + wm * 32 + i * 16 + gid;
            #pragma unroll
            for (int j = 0; j < 8; j++) {
                int col = n0 + wn * 64 + j * 8 + tig * 2;
                float b0 = __ldg(bias + col);
                float b1 = __ldg(bias + col + 1);
                __half2 h0 = __floats2half2_rn(w * gelu_t(c[i][j][0] + b0),
                                               w * gelu_t(c[i][j][1] + b1));
                __half2 h1 = __floats2half2_rn(w * gelu_t(c[i][j][2] + b0),
                                               w * gelu_t(c[i][j][3] + b1));
                *reinterpret_cast<__half2*>(hout + (size_t)r0i * HH + col) = h0;
                *reinterpret_cast<__half2*>(hout + (size_t)(r0i + 8) * HH + col) = h1;
                c[i][j][0] = c[i][j][1] = c[i][j][2] = c[i][j][3] = 0.f;   // reset for next tile
            }
        }
    };

    issue(0, 0);
    issue(1, 1);

    for (int it = 0; it < nch; ++it) {
        if (it + 1 < nch) asm volatile("cp.async.wait_group 1;" ::: "memory");
        else              asm volatile("cp.async.wait_group 0;" ::: "memory");
        __syncthreads();
        if (it + 2 < nch) issue(it + 2, (it + 2) % SS);

        uint32_t sAb = sbase + (it % SS) * STG_BYTES;
        uint32_t sBb = sAb + TILE_BYTES;
        #pragma unroll
        for (int kk = 0; kk < 4; kk++) {
            uint32_t a[2][4];
            #pragma unroll
            for (int i = 0; i < 2; i++) {
                int row = wm * 32 + i * 16 + (lane & 15);
                uint32_t off = (uint32_t)(row * 128 + kk * 32 + ((lane >> 4) & 1) * 16);
                off ^= (off >> 3) & 0x70;
                ldm4(a[i], sAb + off);
            }
            uint32_t b[8][2];
            #pragma unroll
            for (int jp = 0; jp < 4; jp++) {
                int n = wn * 64 + jp * 16 + ((lane >> 4) & 1) * 8 + (lane & 7);
                uint32_t off = (uint32_t)(n * 128 + kk * 32 + ((lane >> 3) & 1) * 16);
                off ^= (off >> 3) & 0x70;
                uint32_t r4[4];
                ldm4(r4, sBb + off);
                b[2 * jp][0] = r4[0]; b[2 * jp][1] = r4[1];
                b[2 * jp + 1][0] = r4[2]; b[2 * jp + 1][1] = r4[3];
            }
            #pragma unroll
            for (int i = 0; i < 2; i++)
                #pragma unroll
                for (int j = 0; j < 8; j++)
                    mma16816(c[i][j], a[i], b[j]);
        }
        if ((it & (NCHT - 1)) == NCHT - 1)
            epilogue(it >> 4);          // mid-stream epilogue; loads for next tile already in flight
    }
}

// ---------------- GEMM2: split-K(2) x segment-concat. P[zk] = sum over segs, K-half zk ----------------
__global__ void __launch_bounds__(256, 2) k_mma2()
{
    int bm = blockIdx.x, bn = blockIdx.y, zk = blockIdx.z;   // zk in {0,1}
    __shared__ const __half* sA[1 + NE];
    __shared__ const __half* sB[1 + NE];
    __shared__ int sNs;

    if (threadIdx.x == 0) {
        int ns = 0;
        sA[ns] = g_H; sB[ns] = g_W2s; ns++;
        for (int e = 0; e < NE; e++) {
            if (tile_weight(e, bm) > 0.f) {
                sA[ns] = g_H + (size_t)(e + 1) * MT * HH;
                sB[ns] = g_W2e + (size_t)e * DD * HH;
                ns++;
            }
        }
        sNs = ns;
    }
    __syncthreads();
    int ns = sNs;
    int nch = ns * 32;                  // 32 chunks = K-half (2048) per segment
    int kbase = zk * 2048;

    extern __shared__ __align__(128) char smem[];
    uint32_t sbase = smem_u32(smem);
    int tid = threadIdx.x, lane = tid & 31, wid = tid >> 5;
    int wm = wid & 3, wn = wid >> 2;
    int m0 = bm * 128, n0 = bn * 128;
    float* pout = g_P + (size_t)zk * MT * DD;

    auto issue = [&](int flat, int slot) {
        int seg = flat >> 5;
        int koff = kbase + (flat & 31) * KCH;
        const __half* Ab = sA[seg] + koff;
        const __half* Bb = sB[seg] + koff;
        char* st = smem + slot * STG_BYTES;
        #pragma unroll
        for (int i = 0; i < 4; i++) {
            int idx = tid + i * 256;
            int r = idx >> 3, c8 = idx & 7;
            uint32_t off = (uint32_t)(r * 128 + c8 * 16);
            off ^= (off >> 3) & 0x70;
            cp_async16(st + off, Ab + (size_t)(m0 + r) * HH + c8 * 8);
        }
        #pragma unroll
        for (int i = 0; i < 4; i++) {
            int idx = tid + i * 256;
            int r = idx >> 3, c8 = idx & 7;
            uint32_t off = (uint32_t)(r * 128 + c8 * 16);
            off ^= (off >> 3) & 0x70;
            cp_async16(st + TILE_BYTES + off, Bb + (size_t)(n0 + r) * HH + c8 * 8);
        }
        cp_commit();
    };

    float c[2][8][4];
    #pragma unroll
    for (int i = 0; i < 2; i++)
        #pragma unroll
        for (int j = 0; j < 8; j++)
            #pragma unroll
            for (int q = 0; q < 4; q++) c[i][j][q] = 0.f;

    issue(0, 0);
    issue(1, 1);

    for (int it = 0; it < nch; ++it) {
        if (it + 1 < nch) asm volatile("cp.async.wait_group 1;" ::: "memory");
        else              asm volatile("cp.async.wait_group 0;" ::: "memory");
        __syncthreads();
        if (it + 2 < nch) issue(it + 2, (it + 2) % SS);

        uint32_t sAb = sbase + (it % SS) * STG_BYTES;
        uint32_t sBb = sAb + TILE_BYTES;
        #pragma unroll
        for (int kk = 0; kk < 4; kk++) {
            uint32_t a[2][4];
            #pragma unroll
            for (int i = 0; i < 2; i++) {
                int row = wm * 32 + i * 16 + (lane & 15);
                uint32_t off = (uint32_t)(row * 128 + kk * 32 + ((lane >> 4) & 1) * 16);
                off ^= (off >> 3) & 0x70;
                ldm4(a[i], sAb + off);
            }
            uint32_t b[8][2];
            #pragma unroll
            for (int jp = 0; jp < 4; jp++) {
                int n = wn * 64 + jp * 16 + ((lane >> 4) & 1) * 8 + (lane & 7);
                uint32_t off = (uint32_t)(n * 128 + kk * 32 + ((lane >> 3) & 1) * 16);
                off ^= (off >> 3) & 0x70;
                uint32_t r4[4];
                ldm4(r4, sBb + off);
                b[2 * jp][0] = r4[0]; b[2 * jp][1] = r4[1];
                b[2 * jp + 1][0] = r4[2]; b[2 * jp + 1][1] = r4[3];
            }
            #pragma unroll
            for (int i = 0; i < 2; i++)
                #pragma unroll
                for (int j = 0; j < 8; j++)
                    mma16816(c[i][j], a[i], b[j]);
        }
    }

    int gid = lane >> 2, tig = lane & 3;
    #pragma unroll
    for (int i = 0; i < 2; i++) {
        int r0i = m0 + wm * 32 + i * 16 + gid;
        #pragma unroll
        for (int j = 0; j < 8; j++) {
            int col = n0 + wn * 64 + j * 8 + tig * 2;
            *reinterpret_cast<float2*>(pout + (size_t)r0i * DD + col) =
                make_float2(c[i][j][0], c[i][j][1]);
            *reinterpret_cast<float2*>(pout + (size_t)(r0i + 8) * DD + col) =
                make_float2(c[i][j][2], c[i][j][3]);
        }
    }
}

// ---------------- reduce: out = P0 + P1 + b_sh + sum_e w*mask*b2_e ----------------
__global__ void k_reduce(const float* __restrict__ b_sh, const float* __restrict__ b_ex,
                         float* __restrict__ out)
{
    int bm = blockIdx.x;
    int bn = blockIdx.y;
    float we[NE];
    #pragma unroll
    for (int e = 0; e < NE; e++) we[e] = tile_weight(e, bm);

    int tid = threadIdx.x;
    size_t base = (size_t)bm * 128 * DD + bn * 128;
    for (int q = tid; q < 4096; q += 256) {
        int r = q >> 5;
        int c4 = (q & 31) << 2;
        size_t off = base + (size_t)r * DD + c4;
        int col = bn * 128 + c4;
        float4 acc = *reinterpret_cast<const float4*>(g_P + off);
        float4 p1  = *reinterpret_cast<const float4*>(g_P + (size_t)MT * DD + off);
        float4 bs  = *reinterpret_cast<const float4*>(b_sh + col);
        acc.x += p1.x + bs.x; acc.y += p1.y + bs.y;
        acc.z += p1.z + bs.z; acc.w += p1.w + bs.w;
        #pragma unroll
        for (int e = 0; e < NE; e++) {
            if (we[e] > 0.f) {
                float4 be = *reinterpret_cast<const float4*>(b_ex + (size_t)e * DD + col);
                acc.x += we[e] * be.x; acc.y += we[e] * be.y;
                acc.z += we[e] * be.z; acc.w += we[e] * be.w;
            }
        }
        *reinterpret_cast<float4*>(out + off) = acc;
    }
}

// ---------------- launch ----------------
extern "C" void kernel_launch(void* const* d_in, const int* in_sizes, int n_in,
                              void* d_out, int out_size)
{
    (void)in_sizes; (void)n_in; (void)out_size;
    const float* x         = (const float*)d_in[0];
    const float* time_cond = (const float*)d_in[1];
    const float* gate_w    = (const float*)d_in[2];
    const float* gate_b    = (const float*)d_in[3];
    const float* time_w    = (const float*)d_in[4];
    const float* time_b    = (const float*)d_in[5];
    const float* ew1       = (const float*)d_in[6];
    const float* eb1       = (const float*)d_in[7];
    const float* ew2       = (const float*)d_in[8];
    const float* eb2       = (const float*)d_in[9];
    const float* sw1       = (const float*)d_in[10];
    const float* sb1       = (const float*)d_in[11];
    const float* sw2       = (const float*)d_in[12];
    const float* sb2       = (const float*)d_in[13];
    float* out = (float*)d_out;

    cudaFuncSetAttribute(k_mma1, cudaFuncAttributeMaxDynamicSharedMemorySize, GEMM_SMEM);
    cudaFuncSetAttribute(k_mma2, cudaFuncAttributeMaxDynamicSharedMemorySize, GEMM_SMEM);

    // 1) conversions + gating stage A, one launch
    k_conv<<<dim3(1024, 1, 2 * NE + 4), dim3(32, 8)>>>(x, ew1, sw1, ew2, sw2);
    // 2) gating stage B
    k_gate<<<8, 256>>>(gate_w, gate_b, time_cond, time_w, time_b);
    // 3) GEMM1: 2 N-tiles per CTA; shared + 4 experts; inactive tiles exit
    k_mma1<<<dim3(MT / 128, HH / 256, 5), 256, GEMM_SMEM>>>(sb1, eb1);
    // 4) GEMM2: split-K(2) with in-CTA segment concat -> 2 fp32 partials
    k_mma2<<<dim3(MT / 128, DD / 128, KSPLIT), 256, GEMM_SMEM>>>();
    // 5) combine partials + biases into out (single deterministic write)
    k_reduce<<<dim3(MT / 128, DD / 128), 256>>>(sb2, eb2, out);
}

// round 15
// speedup vs baseline: 1.0415x; 1.0097x over previous
#include <cuda_runtime.h>
#include <cuda_fp16.h>
#include <cstdint>

#define DD 1024
#define HH 4096
#define NB 8
#define LL 768
#define MT 6144   // NB*LL
#define NE 4

#define KCH 64               // K halfs per chunk (128B rows)
#define SS 3                 // pipeline stages
#define TILE_BYTES 16384     // 128 rows x 128B
#define STG_BYTES 32768      // A tile + B tile
#define GEMM_SMEM (SS * STG_BYTES)   // 96 KB -> 2 CTAs/SM
#define KSPLIT 2             // GEMM2 split-K ways

// ---------------- scratch (device globals; no allocation) ----------------
__device__ __align__(256) __half g_Xh[(size_t)MT * DD];
__device__ __align__(256) __half g_W1e[(size_t)NE * HH * DD];  // W1^T per expert: [H][D]
__device__ __align__(256) __half g_W2e[(size_t)NE * DD * HH];  // W2^T per expert: [D][H]
__device__ __align__(256) __half g_W1s[(size_t)HH * DD];       // sw1^T
__device__ __align__(256) __half g_W2s[(size_t)DD * HH];       // sw2^T
__device__ __align__(256) __half g_H[(size_t)5 * MT * HH];     // [shared, e0..e3] hidden
__device__ __align__(256) float  g_P[(size_t)KSPLIT * MT * DD]; // GEMM2 split-K partials
__device__ float  g_partial[NB * 6 * DD];
__device__ float  g_wbe[NB * NE];

// ---------------- helpers ----------------
__device__ __forceinline__ uint32_t smem_u32(const void* p) {
    uint32_t a;
    asm("{ .reg .u64 t; cvta.to.shared.u64 t, %1; cvt.u32.u64 %0, t; }" : "=r"(a) : "l"(p));
    return a;
}
__device__ __forceinline__ void cp_async16(void* smem, const void* gmem) {
    unsigned s = (unsigned)__cvta_generic_to_shared(smem);
    asm volatile("cp.async.cg.shared.global [%0], [%1], 16;\n" :: "r"(s), "l"(gmem) : "memory");
}
__device__ __forceinline__ void cp_commit() { asm volatile("cp.async.commit_group;\n" ::: "memory"); }

__device__ __forceinline__ void ldm4(uint32_t* r, uint32_t addr) {
    asm volatile("ldmatrix.sync.aligned.m8n8.x4.shared.b16 {%0,%1,%2,%3}, [%4];"
        : "=r"(r[0]), "=r"(r[1]), "=r"(r[2]), "=r"(r[3]) : "r"(addr));
}
__device__ __forceinline__ void mma16816(float* c, const uint32_t* a, const uint32_t* b) {
    asm volatile(
        "mma.sync.aligned.m16n8k16.row.col.f32.f16.f16.f32 "
        "{%0,%1,%2,%3}, {%4,%5,%6,%7}, {%8,%9}, {%0,%1,%2,%3};"
        : "+f"(c[0]), "+f"(c[1]), "+f"(c[2]), "+f"(c[3])
        : "r"(a[0]), "r"(a[1]), "r"(a[2]), "r"(a[3]), "r"(b[0]), "r"(b[1]));
}

// fast GELU (tanh approx via single-instruction MUFU tanh)
__device__ __forceinline__ float gelu_t(float v) {
    float c = 0.7978845608028654f * (v + 0.044715f * v * v * v);
    float t;
    asm("tanh.approx.f32 %0, %1;" : "=f"(t) : "f"(c));
    return 0.5f * v * (1.f + t);
}

// per-M-tile weight: batch gating weight x third-mask; exact 0 => skip tile
__device__ __forceinline__ float tile_weight(int expert, int bm) {
    if (expert < 0) return 1.f;
    int b = bm / 6;             // 6 tiles of 128 tokens per batch
    int third = (bm % 6) >> 1;  // 0 head, 1 wrist, 2 proprio
    if (expert == 1 && third == 1) return 0.f;
    if (expert == 2 && third == 0) return 0.f;
    return g_wbe[b * NE + expert];
}

// ---------------- x convert + gating stage A (main stream) ----------------
// z == 0: x fp32 -> fp16 into g_Xh (grid-stride)
// z == 1: gating stage A partial sums (blocks 0..47)
__global__ void k_convx(const float* __restrict__ x) {
    int z = blockIdx.z;
    int ltid = threadIdx.x;
    if (z == 0) {
        int n4 = MT * DD / 4;
        int stride = gridDim.x * 256;
        for (int i = ltid + blockIdx.x * 256; i < n4; i += stride) {
            float4 v = reinterpret_cast<const float4*>(x)[i];
            __half2* d2 = reinterpret_cast<__half2*>(g_Xh) + (size_t)i * 2;
            d2[0] = __floats2half2_rn(v.x, v.y);
            d2[1] = __floats2half2_rn(v.z, v.w);
        }
        return;
    }
    // stage A
    if (blockIdx.x >= NB * 6) return;
    int b = blockIdx.x / 6, c = blockIdx.x % 6;
    const float* base = x + ((size_t)(b * LL + c * 128)) * DD;
    for (int d = ltid; d < DD; d += 256) {
        float s = 0.f;
        #pragma unroll 4
        for (int l = 0; l < 128; ++l) s += base[(size_t)l * DD + d];
        g_partial[(b * 6 + c) * DD + d] = s;
    }
}

// ---------------- weight transpose kernels (side stream) ----------------
// W==0: W1 family [D,H] -> [H,D] (z = 0..3 experts, z = 4 shared)
// W==1: W2 family [H,D] -> [D,H]
template<int W>
__global__ void k_convw(const float* __restrict__ src_e, const float* __restrict__ src_s) {
    int z = blockIdx.z;
    const float* src;
    __half* dst;
    int R = (W == 0) ? DD : HH;
    int C = (W == 0) ? HH : DD;
    if (z < NE) {
        src = src_e + (size_t)z * R * C;
        dst = ((W == 0) ? g_W1e : g_W2e) + (size_t)z * R * C;
    } else {
        src = src_s;
        dst = (W == 0) ? g_W1s : g_W2s;
    }
    int nCB = C / 64;
    int bx = blockIdx.x % nCB;
    int by = blockIdx.x / nCB;
    if (by >= R / 64) return;
    __shared__ float t[64][65];
    int c0 = bx * 64, r0 = by * 64;
    int tx = threadIdx.x, ty = threadIdx.y;
    #pragma unroll
    for (int j = 0; j < 8; j++) {
        int row = ty + j * 8;
        const float2* sp = reinterpret_cast<const float2*>(src + (size_t)(r0 + row) * C + c0);
        float2 v = sp[tx];              // cols 2tx, 2tx+1  (LDG.64)
        t[row][2 * tx]     = v.x;
        t[row][2 * tx + 1] = v.y;
    }
    __syncthreads();
    #pragma unroll
    for (int j = 0; j < 8; j++) {
        int cc = ty + j * 8;
        __half2 v = __floats2half2_rn(t[2 * tx][cc], t[2 * tx + 1][cc]);
        *reinterpret_cast<__half2*>(dst + (size_t)(c0 + cc) * R + r0 + 2 * tx) = v;
    }
}

// ---------------- gating stage B ----------------
__global__ void k_gate(const float* __restrict__ gate_w, const float* __restrict__ gate_b,
                       const float* __restrict__ time_cond, const float* __restrict__ time_w,
                       const float* __restrict__ time_b)
{
    int b = blockIdx.x, t = threadIdx.x;
    __shared__ float red[12][256];
    float acc[12];
    #pragma unroll
    for (int k = 0; k < 12; k++) acc[k] = 0.f;
    for (int d = t; d < DD; d += 256) {
        float h = g_partial[(b*6+0)*DD+d] + g_partial[(b*6+1)*DD+d];
        float w = g_partial[(b*6+2)*DD+d] + g_partial[(b*6+3)*DD+d];
        float p = g_partial[(b*6+4)*DD+d] + g_partial[(b*6+5)*DD+d];
        float full = (h + w + p) * (1.f / 768.f);
        float hp   = (h + p) * (1.f / 512.f);
        float wp   = (w + p) * (1.f / 512.f);
        #pragma unroll
        for (int e = 0; e < 4; e++)
            acc[e] += full * gate_w[d*4+e] + hp * gate_w[(DD+d)*4+e] + wp * gate_w[(2*DD+d)*4+e];
        float tc = time_cond[b * DD + d];
        float s  = tc / (1.f + expf(-tc));   // silu
        #pragma unroll
        for (int j = 0; j < 8; j++) acc[4 + j] += s * time_w[d*8 + j];
    }
    #pragma unroll
    for (int k = 0; k < 12; k++) red[k][t] = acc[k];
    __syncthreads();
    for (int s = 128; s > 0; s >>= 1) {
        if (t < s) {
            #pragma unroll
            for (int k = 0; k < 12; k++) red[k][t] += red[k][t + s];
        }
        __syncthreads();
    }
    if (t == 0) {
        float logit[4], prob[4];
        #pragma unroll
        for (int e = 0; e < 4; e++) {
            float sc = red[4 + e][0] + time_b[e];
            float sh = red[8 + e][0] + time_b[4 + e];
            logit[e] = (red[e][0] + gate_b[e]) * (1.f + sc) + sh;
        }
        float mx = fmaxf(fmaxf(logit[0], logit[1]), fmaxf(logit[2], logit[3]));
        float sum = 0.f;
        for (int e = 0; e < 4; e++) { prob[e] = expf(logit[e] - mx); sum += prob[e]; }
        for (int e = 0; e < 4; e++) prob[e] /= sum;
        int i1 = 0;
        for (int e = 1; e < 4; e++) if (prob[e] > prob[i1]) i1 = e;
        int i2 = -1;
        for (int e = 0; e < 4; e++) if (e != i1 && (i2 < 0 || prob[e] > prob[i2])) i2 = e;
        float denom = prob[i1] + prob[i2] + 1e-8f;
        #pragma unroll
        for (int e = 0; e < 4; e++) g_wbe[b * NE + e] = 0.f;
        g_wbe[b * NE + i1] = prob[i1] / denom;
        g_wbe[b * NE + i2] = prob[i2] / denom;
    }
}

// ---------------- GEMM1: 2 N-tiles per CTA, continuous 32-chunk pipeline ----------------
// H[z] = w * gelu(X @ W1[z] + b1[z]);  z = 0 shared, 1..4 experts
__global__ void __launch_bounds__(256, 2) k_mma1(
    const float* __restrict__ b_sh, const float* __restrict__ b_ex)
{
    constexpr int NCHT = DD / KCH;      // 16 chunks per tile
    constexpr int NT = 2;               // tiles per CTA
    constexpr int nch = NCHT * NT;      // 32 chunks total

    int bm = blockIdx.x, bn0 = blockIdx.y * NT, z = blockIdx.z;
    float w = tile_weight(z - 1, bm);
    if (w == 0.f) return;

    const __half* A = g_Xh;
    const __half* B = (z == 0) ? g_W1s : (g_W1e + (size_t)(z - 1) * HH * DD);
    const float* bias = (z == 0) ? b_sh : (b_ex + (size_t)(z - 1) * HH);
    __half* hout = g_H + (size_t)z * MT * HH;

    extern __shared__ __align__(128) char smem[];
    uint32_t sbase = smem_u32(smem);
    int tid = threadIdx.x, lane = tid & 31, wid = tid >> 5;
    int wm = wid & 3, wn = wid >> 2;
    int m0 = bm * 128;

    auto issue = [&](int flat, int slot) {
        int tile  = flat >> 4;          // 0..1
        int chunk = flat & (NCHT - 1);
        int koff = chunk * KCH;
        int n0 = (bn0 + tile) * 128;
        const __half* Ab = A + koff;
        const __half* Bb = B + koff;
        char* st = smem + slot * STG_BYTES;
        #pragma unroll
        for (int i = 0; i < 4; i++) {
            int idx = tid + i * 256;
            int r = idx >> 3, c8 = idx & 7;
            uint32_t off = (uint32_t)(r * 128 + c8 * 16);
            off ^= (off >> 3) & 0x70;
            cp_async16(st + off, Ab + (size_t)(m0 + r) * DD + c8 * 8);
        }
        #pragma unroll
        for (int i = 0; i < 4; i++) {
            int idx = tid + i * 256;
            int r = idx >> 3, c8 = idx & 7;
            uint32_t off = (uint32_t)(r * 128 + c8 * 16);
            off ^= (off >> 3) & 0x70;
            cp_async16(st + TILE_BYTES + off, Bb + (size_t)(n0 + r) * DD + c8 * 8);
        }
        cp_commit();
    };

    float c[2][8][4];
    #pragma unroll
    for (int i = 0; i < 2; i++)
        #pragma unroll
        for (int j = 0; j < 8; j++)
            #pragma unroll
            for (int q = 0; q < 4; q++) c[i][j][q] = 0.f;

    int gid = lane >> 2, tig = lane & 3;
    auto epilogue = [&](int tile) {
        int n0 = (bn0 + tile) * 128;
        #pragma unroll
        for (int i = 0; i < 2; i++) {
            int r0i = m0 + wm * 32 + i * 16 + gid;
            #pragma unroll
            for (int j = 0; j < 8; j++) {
                int col = n0 + wn * 64 + j * 8 + tig * 2;
                float b0 = __ldg(bias + col);
                float b1 = __ldg(bias + col + 1);
                __half2 h0 = __floats2half2_rn(w * gelu_t(c[i][j][0] + b0),
                                               w * gelu_t(c[i][j][1] + b1));
                __half2 h1 = __floats2half2_rn(w * gelu_t(c[i][j][2] + b0),
                                               w * gelu_t(c[i][j][3] + b1));
                *reinterpret_cast<__half2*>(hout + (size_t)r0i * HH + col) = h0;
                *reinterpret_cast<__half2*>(hout + (size_t)(r0i + 8) * HH + col) = h1;
                c[i][j][0] = c[i][j][1] = c[i][j][2] = c[i][j][3] = 0.f;   // reset for next tile
            }
        }
    };

    issue(0, 0);
    issue(1, 1);

    for (int it = 0; it < nch; ++it) {
        if (it + 1 < nch) asm volatile("cp.async.wait_group 1;" ::: "memory");
        else              asm volatile("cp.async.wait_group 0;" ::: "memory");
        __syncthreads();
        if (it + 2 < nch) issue(it + 2, (it + 2) % SS);

        uint32_t sAb = sbase + (it % SS) * STG_BYTES;
        uint32_t sBb = sAb + TILE_BYTES;
        #pragma unroll
        for (int kk = 0; kk < 4; kk++) {
            uint32_t a[2][4];
            #pragma unroll
            for (int i = 0; i < 2; i++) {
                int row = wm * 32 + i * 16 + (lane & 15);
                uint32_t off = (uint32_t)(row * 128 + kk * 32 + ((lane >> 4) & 1) * 16);
                off ^= (off >> 3) & 0x70;
                ldm4(a[i], sAb + off);
            }
            uint32_t b[8][2];
            #pragma unroll
            for (int jp = 0; jp < 4; jp++) {
                int n = wn * 64 + jp * 16 + ((lane >> 4) & 1) * 8 + (lane & 7);
                uint32_t off = (uint32_t)(n * 128 + kk * 32 + ((lane >> 3) & 1) * 16);
                off ^= (off >> 3) & 0x70;
                uint32_t r4[4];
                ldm4(r4, sBb + off);
                b[2 * jp][0] = r4[0]; b[2 * jp][1] = r4[1];
                b[2 * jp + 1][0] = r4[2]; b[2 * jp + 1][1] = r4[3];
            }
            #pragma unroll
            for (int i = 0; i < 2; i++)
                #pragma unroll
                for (int j = 0; j < 8; j++)
                    mma16816(c[i][j], a[i], b[j]);
        }
        if ((it & (NCHT - 1)) == NCHT - 1)
            epilogue(it >> 4);          // mid-stream epilogue; loads for next tile already in flight
    }
}

// ---------------- GEMM2: split-K(2) x segment-concat. P[zk] = sum over segs, K-half zk ----------------
__global__ void __launch_bounds__(256, 2) k_mma2()
{
    int bm = blockIdx.x, bn = blockIdx.y, zk = blockIdx.z;   // zk in {0,1}
    __shared__ const __half* sA[1 + NE];
    __shared__ const __half* sB[1 + NE];
    __shared__ int sNs;

    if (threadIdx.x == 0) {
        int ns = 0;
        sA[ns] = g_H; sB[ns] = g_W2s; ns++;
        for (int e = 0; e < NE; e++) {
            if (tile_weight(e, bm) > 0.f) {
                sA[ns] = g_H + (size_t)(e + 1) * MT * HH;
                sB[ns] = g_W2e + (size_t)e * DD * HH;
                ns++;
            }
        }
        sNs = ns;
    }
    __syncthreads();
    int ns = sNs;
    int nch = ns * 32;                  // 32 chunks = K-half (2048) per segment
    int kbase = zk * 2048;

    extern __shared__ __align__(128) char smem[];
    uint32_t sbase = smem_u32(smem);
    int tid = threadIdx.x, lane = tid & 31, wid = tid >> 5;
    int wm = wid & 3, wn = wid >> 2;
    int m0 = bm * 128, n0 = bn * 128;
    float* pout = g_P + (size_t)zk * MT * DD;

    auto issue = [&](int flat, int slot) {
        int seg = flat >> 5;
        int koff = kbase + (flat & 31) * KCH;
        const __half* Ab = sA[seg] + koff;
        const __half* Bb = sB[seg] + koff;
        char* st = smem + slot * STG_BYTES;
        #pragma unroll
        for (int i = 0; i < 4; i++) {
            int idx = tid + i * 256;
            int r = idx >> 3, c8 = idx & 7;
            uint32_t off = (uint32_t)(r * 128 + c8 * 16);
            off ^= (off >> 3) & 0x70;
            cp_async16(st + off, Ab + (size_t)(m0 + r) * HH + c8 * 8);
        }
        #pragma unroll
        for (int i = 0; i < 4; i++) {
            int idx = tid + i * 256;
            int r = idx >> 3, c8 = idx & 7;
            uint32_t off = (uint32_t)(r * 128 + c8 * 16);
            off ^= (off >> 3) & 0x70;
            cp_async16(st + TILE_BYTES + off, Bb + (size_t)(n0 + r) * HH + c8 * 8);
        }
        cp_commit();
    };

    float c[2][8][4];
    #pragma unroll
    for (int i = 0; i < 2; i++)
        #pragma unroll
        for (int j = 0; j < 8; j++)
            #pragma unroll
            for (int q = 0; q < 4; q++) c[i][j][q] = 0.f;

    issue(0, 0);
    issue(1, 1);

    for (int it = 0; it < nch; ++it) {
        if (it + 1 < nch) asm volatile("cp.async.wait_group 1;" ::: "memory");
        else              asm volatile("cp.async.wait_group 0;" ::: "memory");
        __syncthreads();
        if (it + 2 < nch) issue(it + 2, (it + 2) % SS);

        uint32_t sAb = sbase + (it % SS) * STG_BYTES;
        uint32_t sBb = sAb + TILE_BYTES;
        #pragma unroll
        for (int kk = 0; kk < 4; kk++) {
            uint32_t a[2][4];
            #pragma unroll
            for (int i = 0; i < 2; i++) {
                int row = wm * 32 + i * 16 + (lane & 15);
                uint32_t off = (uint32_t)(row * 128 + kk * 32 + ((lane >> 4) & 1) * 16);
                off ^= (off >> 3) & 0x70;
                ldm4(a[i], sAb + off);
            }
            uint32_t b[8][2];
            #pragma unroll
            for (int jp = 0; jp < 4; jp++) {
                int n = wn * 64 + jp * 16 + ((lane >> 4) & 1) * 8 + (lane & 7);
                uint32_t off = (uint32_t)(n * 128 + kk * 32 + ((lane >> 3) & 1) * 16);
                off ^= (off >> 3) & 0x70;
                uint32_t r4[4];
                ldm4(r4, sBb + off);
                b[2 * jp][0] = r4[0]; b[2 * jp][1] = r4[1];
                b[2 * jp + 1][0] = r4[2]; b[2 * jp + 1][1] = r4[3];
            }
            #pragma unroll
            for (int i = 0; i < 2; i++)
                #pragma unroll
                for (int j = 0; j < 8; j++)
                    mma16816(c[i][j], a[i], b[j]);
        }
    }

    int gid = lane >> 2, tig = lane & 3;
    #pragma unroll
    for (int i = 0; i < 2; i++) {
        int r0i = m0 + wm * 32 + i * 16 + gid;
        #pragma unroll
        for (int j = 0; j < 8; j++) {
            int col = n0 + wn * 64 + j * 8 + tig * 2;
            *reinterpret_cast<float2*>(pout + (size_t)r0i * DD + col) =
                make_float2(c[i][j][0], c[i][j][1]);
            *reinterpret_cast<float2*>(pout + (size_t)(r0i + 8) * DD + col) =
                make_float2(c[i][j][2], c[i][j][3]);
        }
    }
}

// ---------------- reduce: out = P0 + P1 + b_sh + sum_e w*mask*b2_e ----------------
__global__ void k_reduce(const float* __restrict__ b_sh, const float* __restrict__ b_ex,
                         float* __restrict__ out)
{
    int bm = blockIdx.x;
    int bn = blockIdx.y;
    float we[NE];
    #pragma unroll
    for (int e = 0; e < NE; e++) we[e] = tile_weight(e, bm);

    int tid = threadIdx.x;
    size_t base = (size_t)bm * 128 * DD + bn * 128;
    for (int q = tid; q < 4096; q += 256) {
        int r = q >> 5;
        int c4 = (q & 31) << 2;
        size_t off = base + (size_t)r * DD + c4;
        int col = bn * 128 + c4;
        float4 acc = *reinterpret_cast<const float4*>(g_P + off);
        float4 p1  = *reinterpret_cast<const float4*>(g_P + (size_t)MT * DD + off);
        float4 bs  = *reinterpret_cast<const float4*>(b_sh + col);
        acc.x += p1.x + bs.x; acc.y += p1.y + bs.y;
        acc.z += p1.z + bs.z; acc.w += p1.w + bs.w;
        #pragma unroll
        for (int e = 0; e < NE; e++) {
            if (we[e] > 0.f) {
                float4 be = *reinterpret_cast<const float4*>(b_ex + (size_t)e * DD + col);
                acc.x += we[e] * be.x; acc.y += we[e] * be.y;
                acc.z += we[e] * be.z; acc.w += we[e] * be.w;
            }
        }
        *reinterpret_cast<float4*>(out + off) = acc;
    }
}

// ---------------- launch ----------------
extern "C" void kernel_launch(void* const* d_in, const int* in_sizes, int n_in,
                              void* d_out, int out_size)
{
    (void)in_sizes; (void)n_in; (void)out_size;
    const float* x         = (const float*)d_in[0];
    const float* time_cond = (const float*)d_in[1];
    const float* gate_w    = (const float*)d_in[2];
    const float* gate_b    = (const float*)d_in[3];
    const float* time_w    = (const float*)d_in[4];
    const float* time_b    = (const float*)d_in[5];
    const float* ew1       = (const float*)d_in[6];
    const float* eb1       = (const float*)d_in[7];
    const float* ew2       = (const float*)d_in[8];
    const float* eb2       = (const float*)d_in[9];
    const float* sw1       = (const float*)d_in[10];
    const float* sb1       = (const float*)d_in[11];
    const float* sw2       = (const float*)d_in[12];
    const float* sb2       = (const float*)d_in[13];
    float* out = (float*)d_out;

    // one-time host resources (no device memory involved)
    static cudaStream_t s1 = nullptr;
    static cudaEvent_t ev_fork = nullptr, ev_w1 = nullptr, ev_w2 = nullptr;
    if (s1 == nullptr) {
        cudaStreamCreateWithFlags(&s1, cudaStreamNonBlocking);
        cudaEventCreateWithFlags(&ev_fork, cudaEventDisableTiming);
        cudaEventCreateWithFlags(&ev_w1,   cudaEventDisableTiming);
        cudaEventCreateWithFlags(&ev_w2,   cudaEventDisableTiming);
        cudaFuncSetAttribute(k_mma1, cudaFuncAttributeMaxDynamicSharedMemorySize, GEMM_SMEM);
        cudaFuncSetAttribute(k_mma2, cudaFuncAttributeMaxDynamicSharedMemorySize, GEMM_SMEM);
    }

    // fork side stream from the main (capture-origin) stream
    cudaEventRecord(ev_fork, 0);
    cudaStreamWaitEvent(s1, ev_fork, 0);

    // side stream: weight transposes (W1 first — GEMM1 dependency)
    k_convw<0><<<dim3(1024, 1, NE + 1), dim3(32, 8), 0, s1>>>(ew1, sw1);
    cudaEventRecord(ev_w1, s1);
    k_convw<1><<<dim3(1024, 1, NE + 1), dim3(32, 8), 0, s1>>>(ew2, sw2);
    cudaEventRecord(ev_w2, s1);

    // main stream: x convert + stage A, then gate
    k_convx<<<dim3(1024, 1, 2), 256>>>(x);
    k_gate<<<8, 256>>>(gate_w, gate_b, time_cond, time_w, time_b);

    // GEMM1 needs W1 transposes done
    cudaStreamWaitEvent(0, ev_w1, 0);
    k_mma1<<<dim3(MT / 128, HH / 256, 5), 256, GEMM_SMEM>>>(sb1, eb1);

    // GEMM2 needs W2 transposes done (they overlapped with GEMM1)
    cudaStreamWaitEvent(0, ev_w2, 0);
    k_mma2<<<dim3(MT / 128, DD / 128, KSPLIT), 256, GEMM_SMEM>>>();

    // combine partials + biases into out (single deterministic write)
    k_reduce<<<dim3(MT / 128, DD / 128), 256>>>(sb2, eb2, out);
}

// round 16
// speedup vs baseline: 1.0460x; 1.0043x over previous
#include <cuda_runtime.h>
#include <cuda_fp16.h>
#include <cstdint>

#define DD 1024
#define HH 4096
#define NB 8
#define LL 768
#define MT 6144   // NB*LL
#define NE 4

#define KCH 64               // K halfs per chunk (128B rows)
#define SS 3                 // pipeline stages
#define TILE_BYTES 16384     // 128 rows x 128B
#define STG_BYTES 32768      // A tile + B tile
#define GEMM_SMEM (SS * STG_BYTES)   // 96 KB -> 2 CTAs/SM
#define KSPLIT 2             // GEMM2 split-K ways

// ---------------- scratch (device globals; no allocation) ----------------
__device__ __align__(256) __half g_Xh[(size_t)MT * DD];
__device__ __align__(256) __half g_W1e[(size_t)NE * HH * DD];  // W1^T per expert: [H][D]
__device__ __align__(256) __half g_W2e[(size_t)NE * DD * HH];  // W2^T per expert: [D][H]
__device__ __align__(256) __half g_W1s[(size_t)HH * DD];       // sw1^T
__device__ __align__(256) __half g_W2s[(size_t)DD * HH];       // sw2^T
__device__ __align__(256) __half g_H[(size_t)5 * MT * HH];     // [shared, e0..e3] hidden
__device__ __align__(256) float  g_P[(size_t)KSPLIT * MT * DD]; // GEMM2 split-K partials
__device__ float  g_partial[NB * 6 * DD];
__device__ float  g_wbe[NB * NE];

// ---------------- helpers ----------------
__device__ __forceinline__ uint32_t smem_u32(const void* p) {
    uint32_t a;
    asm("{ .reg .u64 t; cvta.to.shared.u64 t, %1; cvt.u32.u64 %0, t; }" : "=r"(a) : "l"(p));
    return a;
}
__device__ __forceinline__ void cp_async16(void* smem, const void* gmem) {
    unsigned s = (unsigned)__cvta_generic_to_shared(smem);
    asm volatile("cp.async.cg.shared.global [%0], [%1], 16;\n" :: "r"(s), "l"(gmem) : "memory");
}
__device__ __forceinline__ void cp_commit() { asm volatile("cp.async.commit_group;\n" ::: "memory"); }

__device__ __forceinline__ void ldm4(uint32_t* r, uint32_t addr) {
    asm volatile("ldmatrix.sync.aligned.m8n8.x4.shared.b16 {%0,%1,%2,%3}, [%4];"
        : "=r"(r[0]), "=r"(r[1]), "=r"(r[2]), "=r"(r[3]) : "r"(addr));
}
__device__ __forceinline__ void mma16816(float* c, const uint32_t* a, const uint32_t* b) {
    asm volatile(
        "mma.sync.aligned.m16n8k16.row.col.f32.f16.f16.f32 "
        "{%0,%1,%2,%3}, {%4,%5,%6,%7}, {%8,%9}, {%0,%1,%2,%3};"
        : "+f"(c[0]), "+f"(c[1]), "+f"(c[2]), "+f"(c[3])
        : "r"(a[0]), "r"(a[1]), "r"(a[2]), "r"(a[3]), "r"(b[0]), "r"(b[1]));
}

// fast GELU (tanh approx via single-instruction MUFU tanh)
__device__ __forceinline__ float gelu_t(float v) {
    float c = 0.7978845608028654f * (v + 0.044715f * v * v * v);
    float t;
    asm("tanh.approx.f32 %0, %1;" : "=f"(t) : "f"(c));
    return 0.5f * v * (1.f + t);
}

// per-M-tile weight: batch gating weight x third-mask; exact 0 => skip tile
__device__ __forceinline__ float tile_weight(int expert, int bm) {
    if (expert < 0) return 1.f;
    int b = bm / 6;             // 6 tiles of 128 tokens per batch
    int third = (bm % 6) >> 1;  // 0 head, 1 wrist, 2 proprio
    if (expert == 1 && third == 1) return 0.f;
    if (expert == 2 && third == 0) return 0.f;
    return g_wbe[b * NE + expert];
}

// ---------------- x convert (stream s2) ----------------
__global__ void k_convx(const float* __restrict__ x) {
    int n4 = MT * DD / 4;
    int stride = gridDim.x * 256;
    for (int i = threadIdx.x + blockIdx.x * 256; i < n4; i += stride) {
        float4 v = reinterpret_cast<const float4*>(x)[i];
        __half2* d2 = reinterpret_cast<__half2*>(g_Xh) + (size_t)i * 2;
        d2[0] = __floats2half2_rn(v.x, v.y);
        d2[1] = __floats2half2_rn(v.z, v.w);
    }
}

// ---------------- gating stage A (main stream, first) ----------------
__global__ void k_stageA(const float* __restrict__ x) {
    int b = blockIdx.x / 6, c = blockIdx.x % 6;
    const float* base = x + ((size_t)(b * LL + c * 128)) * DD;
    for (int d = threadIdx.x; d < DD; d += 256) {
        float s = 0.f;
        #pragma unroll 4
        for (int l = 0; l < 128; ++l) s += base[(size_t)l * DD + d];
        g_partial[(b * 6 + c) * DD + d] = s;
    }
}

// ---------------- weight transpose kernels (side stream s1) ----------------
// W==0: W1 family [D,H] -> [H,D] (z = 0..3 experts, z = 4 shared)
// W==1: W2 family [H,D] -> [D,H]
template<int W>
__global__ void k_convw(const float* __restrict__ src_e, const float* __restrict__ src_s) {
    int z = blockIdx.z;
    const float* src;
    __half* dst;
    int R = (W == 0) ? DD : HH;
    int C = (W == 0) ? HH : DD;
    if (z < NE) {
        src = src_e + (size_t)z * R * C;
        dst = ((W == 0) ? g_W1e : g_W2e) + (size_t)z * R * C;
    } else {
        src = src_s;
        dst = (W == 0) ? g_W1s : g_W2s;
    }
    int nCB = C / 64;
    int bx = blockIdx.x % nCB;
    int by = blockIdx.x / nCB;
    if (by >= R / 64) return;
    __shared__ float t[64][65];
    int c0 = bx * 64, r0 = by * 64;
    int tx = threadIdx.x, ty = threadIdx.y;
    #pragma unroll
    for (int j = 0; j < 8; j++) {
        int row = ty + j * 8;
        const float2* sp = reinterpret_cast<const float2*>(src + (size_t)(r0 + row) * C + c0);
        float2 v = sp[tx];              // cols 2tx, 2tx+1  (LDG.64)
        t[row][2 * tx]     = v.x;
        t[row][2 * tx + 1] = v.y;
    }
    __syncthreads();
    #pragma unroll
    for (int j = 0; j < 8; j++) {
        int cc = ty + j * 8;
        __half2 v = __floats2half2_rn(t[2 * tx][cc], t[2 * tx + 1][cc]);
        *reinterpret_cast<__half2*>(dst + (size_t)(c0 + cc) * R + r0 + 2 * tx) = v;
    }
}

// ---------------- gating stage B (shuffle reduction) ----------------
__global__ void k_gate(const float* __restrict__ gate_w, const float* __restrict__ gate_b,
                       const float* __restrict__ time_cond, const float* __restrict__ time_w,
                       const float* __restrict__ time_b)
{
    int b = blockIdx.x, t = threadIdx.x;
    int lane = t & 31, wrp = t >> 5;
    __shared__ float red[8][12];
    float acc[12];
    #pragma unroll
    for (int k = 0; k < 12; k++) acc[k] = 0.f;
    for (int d = t; d < DD; d += 256) {
        float h = g_partial[(b*6+0)*DD+d] + g_partial[(b*6+1)*DD+d];
        float w = g_partial[(b*6+2)*DD+d] + g_partial[(b*6+3)*DD+d];
        float p = g_partial[(b*6+4)*DD+d] + g_partial[(b*6+5)*DD+d];
        float full = (h + w + p) * (1.f / 768.f);
        float hp   = (h + p) * (1.f / 512.f);
        float wp   = (w + p) * (1.f / 512.f);
        #pragma unroll
        for (int e = 0; e < 4; e++)
            acc[e] += full * gate_w[d*4+e] + hp * gate_w[(DD+d)*4+e] + wp * gate_w[(2*DD+d)*4+e];
        float tc = time_cond[b * DD + d];
        float s  = tc / (1.f + expf(-tc));   // silu
        #pragma unroll
        for (int j = 0; j < 8; j++) acc[4 + j] += s * time_w[d*8 + j];
    }
    // warp-level reduce all 12 accumulators
    #pragma unroll
    for (int k = 0; k < 12; k++) {
        #pragma unroll
        for (int o = 16; o > 0; o >>= 1)
            acc[k] += __shfl_xor_sync(0xffffffffu, acc[k], o);
    }
    if (lane == 0) {
        #pragma unroll
        for (int k = 0; k < 12; k++) red[wrp][k] = acc[k];
    }
    __syncthreads();
    if (t == 0) {
        float tot[12];
        #pragma unroll
        for (int k = 0; k < 12; k++) {
            float s = red[0][k];
            #pragma unroll
            for (int w2 = 1; w2 < 8; w2++) s += red[w2][k];
            tot[k] = s;
        }
        float logit[4], prob[4];
        #pragma unroll
        for (int e = 0; e < 4; e++) {
            float sc = tot[4 + e] + time_b[e];
            float sh = tot[8 + e] + time_b[4 + e];
            logit[e] = (tot[e] + gate_b[e]) * (1.f + sc) + sh;
        }
        float mx = fmaxf(fmaxf(logit[0], logit[1]), fmaxf(logit[2], logit[3]));
        float sum = 0.f;
        for (int e = 0; e < 4; e++) { prob[e] = expf(logit[e] - mx); sum += prob[e]; }
        for (int e = 0; e < 4; e++) prob[e] /= sum;
        int i1 = 0;
        for (int e = 1; e < 4; e++) if (prob[e] > prob[i1]) i1 = e;
        int i2 = -1;
        for (int e = 0; e < 4; e++) if (e != i1 && (i2 < 0 || prob[e] > prob[i2])) i2 = e;
        float denom = prob[i1] + prob[i2] + 1e-8f;
        #pragma unroll
        for (int e = 0; e < 4; e++) g_wbe[b * NE + e] = 0.f;
        g_wbe[b * NE + i1] = prob[i1] / denom;
        g_wbe[b * NE + i2] = prob[i2] / denom;
    }
}

// ---------------- GEMM1: 2 N-tiles per CTA, continuous 32-chunk pipeline ----------------
// H[z] = w * gelu(X @ W1[z] + b1[z]);  z = 0 shared, 1..4 experts
__global__ void __launch_bounds__(256, 2) k_mma1(
    const float* __restrict__ b_sh, const float* __restrict__ b_ex)
{
    constexpr int NCHT = DD / KCH;      // 16 chunks per tile
    constexpr int NT = 2;               // tiles per CTA
    constexpr int nch = NCHT * NT;      // 32 chunks total

    int bm = blockIdx.x, bn0 = blockIdx.y * NT, z = blockIdx.z;
    float w = tile_weight(z - 1, bm);
    if (w == 0.f) return;

    const __half* A = g_Xh;
    const __half* B = (z == 0) ? g_W1s : (g_W1e + (size_t)(z - 1) * HH * DD);
    const float* bias = (z == 0) ? b_sh : (b_ex + (size_t)(z - 1) * HH);
    __half* hout = g_H + (size_t)z * MT * HH;

    extern __shared__ __align__(128) char smem[];
    uint32_t sbase = smem_u32(smem);
    int tid = threadIdx.x, lane = tid & 31, wid = tid >> 5;
    int wm = wid & 3, wn = wid >> 2;
    int m0 = bm * 128;

    auto issue = [&](int flat, int slot) {
        int tile  = flat >> 4;          // 0..1
        int chunk = flat & (NCHT - 1);
        int koff = chunk * KCH;
        int n0 = (bn0 + tile) * 128;
        const __half* Ab = A + koff;
        const __half* Bb = B + koff;
        char* st = smem + slot * STG_BYTES;
        #pragma unroll
        for (int i = 0; i < 4; i++) {
            int idx = tid + i * 256;
            int r = idx >> 3, c8 = idx & 7;
            uint32_t off = (uint32_t)(r * 128 + c8 * 16);
            off ^= (off >> 3) & 0x70;
            cp_async16(st + off, Ab + (size_t)(m0 + r) * DD + c8 * 8);
        }
        #pragma unroll
        for (int i = 0; i < 4; i++) {
            int idx = tid + i * 256;
            int r = idx >> 3, c8 = idx & 7;
            uint32_t off = (uint32_t)(r * 128 + c8 * 16);
            off ^= (off >> 3) & 0x70;
            cp_async16(st + TILE_BYTES + off, Bb + (size_t)(n0 + r) * DD + c8 * 8);
        }
        cp_commit();
    };

    float c[2][8][4];
    #pragma unroll
    for (int i = 0; i < 2; i++)
        #pragma unroll
        for (int j = 0; j < 8; j++)
            #pragma unroll
            for (int q = 0; q < 4; q++) c[i][j][q] = 0.f;

    int gid = lane >> 2, tig = lane & 3;
    auto epilogue = [&](int tile) {
        int n0 = (bn0 + tile) * 128;
        #pragma unroll
        for (int i = 0; i < 2; i++) {
            int r0i = m0 + wm * 32 + i * 16 + gid;
            #pragma unroll
            for (int j = 0; j < 8; j++) {
                int col = n0 + wn * 64 + j * 8 + tig * 2;
                float b0 = __ldg(bias + col);
                float b1 = __ldg(bias + col + 1);
                __half2 h0 = __floats2half2_rn(w * gelu_t(c[i][j][0] + b0),
                                               w * gelu_t(c[i][j][1] + b1));
                __half2 h1 = __floats2half2_rn(w * gelu_t(c[i][j][2] + b0),
                                               w * gelu_t(c[i][j][3] + b1));
                *reinterpret_cast<__half2*>(hout + (size_t)r0i * HH + col) = h0;
                *reinterpret_cast<__half2*>(hout + (size_t)(r0i + 8) * HH + col) = h1;
                c[i][j][0] = c[i][j][1] = c[i][j][2] = c[i][j][3] = 0.f;   // reset for next tile
            }
        }
    };

    issue(0, 0);
    issue(1, 1);

    for (int it = 0; it < nch; ++it) {
        if (it + 1 < nch) asm volatile("cp.async.wait_group 1;" ::: "memory");
        else              asm volatile("cp.async.wait_group 0;" ::: "memory");
        __syncthreads();
        if (it + 2 < nch) issue(it + 2, (it + 2) % SS);

        uint32_t sAb = sbase + (it % SS) * STG_BYTES;
        uint32_t sBb = sAb + TILE_BYTES;
        #pragma unroll
        for (int kk = 0; kk < 4; kk++) {
            uint32_t a[2][4];
            #pragma unroll
            for (int i = 0; i < 2; i++) {
                int row = wm * 32 + i * 16 + (lane & 15);
                uint32_t off = (uint32_t)(row * 128 + kk * 32 + ((lane >> 4) & 1) * 16);
                off ^= (off >> 3) & 0x70;
                ldm4(a[i], sAb + off);
            }
            uint32_t b[8][2];
            #pragma unroll
            for (int jp = 0; jp < 4; jp++) {
                int n = wn * 64 + jp * 16 + ((lane >> 4) & 1) * 8 + (lane & 7);
                uint32_t off = (uint32_t)(n * 128 + kk * 32 + ((lane >> 3) & 1) * 16);
                off ^= (off >> 3) & 0x70;
                uint32_t r4[4];
                ldm4(r4, sBb + off);
                b[2 * jp][0] = r4[0]; b[2 * jp][1] = r4[1];
                b[2 * jp + 1][0] = r4[2]; b[2 * jp + 1][1] = r4[3];
            }
            #pragma unroll
            for (int i = 0; i < 2; i++)
                #pragma unroll
                for (int j = 0; j < 8; j++)
                    mma16816(c[i][j], a[i], b[j]);
        }
        if ((it & (NCHT - 1)) == NCHT - 1)
            epilogue(it >> 4);          // mid-stream epilogue; loads for next tile already in flight
    }
}

// ---------------- GEMM2: split-K(2) x segment-concat. P[zk] = sum over segs, K-half zk ----------------
__global__ void __launch_bounds__(256, 2) k_mma2()
{
    int bm = blockIdx.x, bn = blockIdx.y, zk = blockIdx.z;   // zk in {0,1}
    __shared__ const __half* sA[1 + NE];
    __shared__ const __half* sB[1 + NE];
    __shared__ int sNs;

    if (threadIdx.x == 0) {
        int ns = 0;
        sA[ns] = g_H; sB[ns] = g_W2s; ns++;
        for (int e = 0; e < NE; e++) {
            if (tile_weight(e, bm) > 0.f) {
                sA[ns] = g_H + (size_t)(e + 1) * MT * HH;
                sB[ns] = g_W2e + (size_t)e * DD * HH;
                ns++;
            }
        }
        sNs = ns;
    }
    __syncthreads();
    int ns = sNs;
    int nch = ns * 32;                  // 32 chunks = K-half (2048) per segment
    int kbase = zk * 2048;

    extern __shared__ __align__(128) char smem[];
    uint32_t sbase = smem_u32(smem);
    int tid = threadIdx.x, lane = tid & 31, wid = tid >> 5;
    int wm = wid & 3, wn = wid >> 2;
    int m0 = bm * 128, n0 = bn * 128;
    float* pout = g_P + (size_t)zk * MT * DD;

    auto issue = [&](int flat, int slot) {
        int seg = flat >> 5;
        int koff = kbase + (flat & 31) * KCH;
        const __half* Ab = sA[seg] + koff;
        const __half* Bb = sB[seg] + koff;
        char* st = smem + slot * STG_BYTES;
        #pragma unroll
        for (int i = 0; i < 4; i++) {
            int idx = tid + i * 256;
            int r = idx >> 3, c8 = idx & 7;
            uint32_t off = (uint32_t)(r * 128 + c8 * 16);
            off ^= (off >> 3) & 0x70;
            cp_async16(st + off, Ab + (size_t)(m0 + r) * HH + c8 * 8);
        }
        #pragma unroll
        for (int i = 0; i < 4; i++) {
            int idx = tid + i * 256;
            int r = idx >> 3, c8 = idx & 7;
            uint32_t off = (uint32_t)(r * 128 + c8 * 16);
            off ^= (off >> 3) & 0x70;
            cp_async16(st + TILE_BYTES + off, Bb + (size_t)(n0 + r) * HH + c8 * 8);
        }
        cp_commit();
    };

    float c[2][8][4];
    #pragma unroll
    for (int i = 0; i < 2; i++)
        #pragma unroll
        for (int j = 0; j < 8; j++)
            #pragma unroll
            for (int q = 0; q < 4; q++) c[i][j][q] = 0.f;

    issue(0, 0);
    issue(1, 1);

    for (int it = 0; it < nch; ++it) {
        if (it + 1 < nch) asm volatile("cp.async.wait_group 1;" ::: "memory");
        else              asm volatile("cp.async.wait_group 0;" ::: "memory");
        __syncthreads();
        if (it + 2 < nch) issue(it + 2, (it + 2) % SS);

        uint32_t sAb = sbase + (it % SS) * STG_BYTES;
        uint32_t sBb = sAb + TILE_BYTES;
        #pragma unroll
        for (int kk = 0; kk < 4; kk++) {
            uint32_t a[2][4];
            #pragma unroll
            for (int i = 0; i < 2; i++) {
                int row = wm * 32 + i * 16 + (lane & 15);
                uint32_t off = (uint32_t)(row * 128 + kk * 32 + ((lane >> 4) & 1) * 16);
                off ^= (off >> 3) & 0x70;
                ldm4(a[i], sAb + off);
            }
            uint32_t b[8][2];
            #pragma unroll
            for (int jp = 0; jp < 4; jp++) {
                int n = wn * 64 + jp * 16 + ((lane >> 4) & 1) * 8 + (lane & 7);
                uint32_t off = (uint32_t)(n * 128 + kk * 32 + ((lane >> 3) & 1) * 16);
                off ^= (off >> 3) & 0x70;
                uint32_t r4[4];
                ldm4(r4, sBb + off);
                b[2 * jp][0] = r4[0]; b[2 * jp][1] = r4[1];
                b[2 * jp + 1][0] = r4[2]; b[2 * jp + 1][1] = r4[3];
            }
            #pragma unroll
            for (int i = 0; i < 2; i++)
                #pragma unroll
                for (int j = 0; j < 8; j++)
                    mma16816(c[i][j], a[i], b[j]);
        }
    }

    int gid = lane >> 2, tig = lane & 3;
    #pragma unroll
    for (int i = 0; i < 2; i++) {
        int r0i = m0 + wm * 32 + i * 16 + gid;
        #pragma unroll
        for (int j = 0; j < 8; j++) {
            int col = n0 + wn * 64 + j * 8 + tig * 2;
            *reinterpret_cast<float2*>(pout + (size_t)r0i * DD + col) =
                make_float2(c[i][j][0], c[i][j][1]);
            *reinterpret_cast<float2*>(pout + (size_t)(r0i + 8) * DD + col) =
                make_float2(c[i][j][2], c[i][j][3]);
        }
    }
}

// ---------------- reduce: out = P0 + P1 + b_sh + sum_e w*mask*b2_e ----------------
__global__ void k_reduce(const float* __restrict__ b_sh, const float* __restrict__ b_ex,
                         float* __restrict__ out)
{
    int bm = blockIdx.x;
    int bn = blockIdx.y;
    float we[NE];
    #pragma unroll
    for (int e = 0; e < NE; e++) we[e] = tile_weight(e, bm);

    int tid = threadIdx.x;
    size_t base = (size_t)bm * 128 * DD + bn * 128;
    for (int q = tid; q < 4096; q += 256) {
        int r = q >> 5;
        int c4 = (q & 31) << 2;
        size_t off = base + (size_t)r * DD + c4;
        int col = bn * 128 + c4;
        float4 acc = *reinterpret_cast<const float4*>(g_P + off);
        float4 p1  = *reinterpret_cast<const float4*>(g_P + (size_t)MT * DD + off);
        float4 bs  = *reinterpret_cast<const float4*>(b_sh + col);
        acc.x += p1.x + bs.x; acc.y += p1.y + bs.y;
        acc.z += p1.z + bs.z; acc.w += p1.w + bs.w;
        #pragma unroll
        for (int e = 0; e < NE; e++) {
            if (we[e] > 0.f) {
                float4 be = *reinterpret_cast<const float4*>(b_ex + (size_t)e * DD + col);
                acc.x += we[e] * be.x; acc.y += we[e] * be.y;
                acc.z += we[e] * be.z; acc.w += we[e] * be.w;
            }
        }
        *reinterpret_cast<float4*>(out + off) = acc;
    }
}

// ---------------- launch ----------------
extern "C" void kernel_launch(void* const* d_in, const int* in_sizes, int n_in,
                              void* d_out, int out_size)
{
    (void)in_sizes; (void)n_in; (void)out_size;
    const float* x         = (const float*)d_in[0];
    const float* time_cond = (const float*)d_in[1];
    const float* gate_w    = (const float*)d_in[2];
    const float* gate_b    = (const float*)d_in[3];
    const float* time_w    = (const float*)d_in[4];
    const float* time_b    = (const float*)d_in[5];
    const float* ew1       = (const float*)d_in[6];
    const float* eb1       = (const float*)d_in[7];
    const float* ew2       = (const float*)d_in[8];
    const float* eb2       = (const float*)d_in[9];
    const float* sw1       = (const float*)d_in[10];
    const float* sb1       = (const float*)d_in[11];
    const float* sw2       = (const float*)d_in[12];
    const float* sb2       = (const float*)d_in[13];
    float* out = (float*)d_out;

    // one-time host resources (no device memory involved)
    static cudaStream_t s1 = nullptr, s2 = nullptr;
    static cudaEvent_t ev_fork = nullptr, ev_w1 = nullptr, ev_w2 = nullptr, ev_x = nullptr;
    if (s1 == nullptr) {
        cudaStreamCreateWithFlags(&s1, cudaStreamNonBlocking);
        cudaStreamCreateWithFlags(&s2, cudaStreamNonBlocking);
        cudaEventCreateWithFlags(&ev_fork, cudaEventDisableTiming);
        cudaEventCreateWithFlags(&ev_w1,   cudaEventDisableTiming);
        cudaEventCreateWithFlags(&ev_w2,   cudaEventDisableTiming);
        cudaEventCreateWithFlags(&ev_x,    cudaEventDisableTiming);
        cudaFuncSetAttribute(k_mma1, cudaFuncAttributeMaxDynamicSharedMemorySize, GEMM_SMEM);
        cudaFuncSetAttribute(k_mma2, cudaFuncAttributeMaxDynamicSharedMemorySize, GEMM_SMEM);
    }

    // fork side streams from the main (capture-origin) stream
    cudaEventRecord(ev_fork, 0);
    cudaStreamWaitEvent(s1, ev_fork, 0);
    cudaStreamWaitEvent(s2, ev_fork, 0);

    // s1: weight transposes (W1 first — GEMM1 dependency; W2 hides under GEMM1)
    k_convw<0><<<dim3(1024, 1, NE + 1), dim3(32, 8), 0, s1>>>(ew1, sw1);
    cudaEventRecord(ev_w1, s1);
    k_convw<1><<<dim3(1024, 1, NE + 1), dim3(32, 8), 0, s1>>>(ew2, sw2);
    cudaEventRecord(ev_w2, s1);

    // s2: x fp32 -> fp16
    k_convx<<<1024, 256, 0, s2>>>(x);
    cudaEventRecord(ev_x, s2);

    // main stream: gating (stage A then B) — no longer behind the x-convert
    k_stageA<<<NB * 6, 256>>>(x);
    k_gate<<<8, 256>>>(gate_w, gate_b, time_cond, time_w, time_b);

    // GEMM1 needs gate + Xh + W1 transposes
    cudaStreamWaitEvent(0, ev_x, 0);
    cudaStreamWaitEvent(0, ev_w1, 0);
    k_mma1<<<dim3(MT / 128, HH / 256, 5), 256, GEMM_SMEM>>>(sb1, eb1);

    // GEMM2 needs W2 transposes (overlapped with GEMM1)
    cudaStreamWaitEvent(0, ev_w2, 0);
    k_mma2<<<dim3(MT / 128, DD / 128, KSPLIT), 256, GEMM_SMEM>>>();

    // combine partials + biases into out (single deterministic write)
    k_reduce<<<dim3(MT / 128, DD / 128), 256>>>(sb2, eb2, out);
}

// round 17
// speedup vs baseline: 1.1175x; 1.0683x over previous
#include <cuda_runtime.h>
#include <cuda_fp16.h>
#include <cstdint>

#define DD 1024
#define HH 4096
#define NB 8
#define LL 768
#define MT 6144   // NB*LL
#define NE 4
#define NSC 48               // stage-A sub-chunks per batch (16 rows each)

#define KCH 64               // K halfs per chunk (128B rows)
#define SS 3                 // pipeline stages
#define TILE_BYTES 16384     // 128 rows x 128B
#define STG_BYTES 32768      // A tile + B tile
#define GEMM_SMEM (SS * STG_BYTES)   // 96 KB -> 2 CTAs/SM
#define KSPLIT 2             // GEMM2 split-K ways

// ---------------- scratch (device globals; no allocation) ----------------
__device__ __align__(256) __half g_Xh[(size_t)MT * DD];
__device__ __align__(256) __half g_W1e[(size_t)NE * HH * DD];  // W1^T per expert: [H][D]
__device__ __align__(256) __half g_W2e[(size_t)NE * DD * HH];  // W2^T per expert: [D][H]
__device__ __align__(256) __half g_W1s[(size_t)HH * DD];       // sw1^T
__device__ __align__(256) __half g_W2s[(size_t)DD * HH];       // sw2^T
__device__ __align__(256) __half g_H[(size_t)5 * MT * HH];     // [shared, e0..e3] hidden
__device__ __align__(256) float  g_P[(size_t)KSPLIT * MT * DD]; // GEMM2 split-K partials
__device__ float  g_partial[NB * NSC * DD];
__device__ float  g_wbe[NB * NE];

// ---------------- helpers ----------------
__device__ __forceinline__ uint32_t smem_u32(const void* p) {
    uint32_t a;
    asm("{ .reg .u64 t; cvta.to.shared.u64 t, %1; cvt.u32.u64 %0, t; }" : "=r"(a) : "l"(p));
    return a;
}
__device__ __forceinline__ void cp_async16(void* smem, const void* gmem) {
    unsigned s = (unsigned)__cvta_generic_to_shared(smem);
    asm volatile("cp.async.cg.shared.global [%0], [%1], 16;\n" :: "r"(s), "l"(gmem) : "memory");
}
__device__ __forceinline__ void cp_commit() { asm volatile("cp.async.commit_group;\n" ::: "memory"); }

__device__ __forceinline__ void ldm4(uint32_t* r, uint32_t addr) {
    asm volatile("ldmatrix.sync.aligned.m8n8.x4.shared.b16 {%0,%1,%2,%3}, [%4];"
        : "=r"(r[0]), "=r"(r[1]), "=r"(r[2]), "=r"(r[3]) : "r"(addr));
}
__device__ __forceinline__ void mma16816(float* c, const uint32_t* a, const uint32_t* b) {
    asm volatile(
        "mma.sync.aligned.m16n8k16.row.col.f32.f16.f16.f32 "
        "{%0,%1,%2,%3}, {%4,%5,%6,%7}, {%8,%9}, {%0,%1,%2,%3};"
        : "+f"(c[0]), "+f"(c[1]), "+f"(c[2]), "+f"(c[3])
        : "r"(a[0]), "r"(a[1]), "r"(a[2]), "r"(a[3]), "r"(b[0]), "r"(b[1]));
}

// fast GELU (tanh approx via single-instruction MUFU tanh)
__device__ __forceinline__ float gelu_t(float v) {
    float c = 0.7978845608028654f * (v + 0.044715f * v * v * v);
    float t;
    asm("tanh.approx.f32 %0, %1;" : "=f"(t) : "f"(c));
    return 0.5f * v * (1.f + t);
}

// per-M-tile weight: batch gating weight x third-mask; exact 0 => skip tile
__device__ __forceinline__ float tile_weight(int expert, int bm) {
    if (expert < 0) return 1.f;
    int b = bm / 6;             // 6 tiles of 128 tokens per batch
    int third = (bm % 6) >> 1;  // 0 head, 1 wrist, 2 proprio
    if (expert == 1 && third == 1) return 0.f;
    if (expert == 2 && third == 0) return 0.f;
    return g_wbe[b * NE + expert];
}

// ---------------- x convert (stream s2) ----------------
__global__ void k_convx(const float* __restrict__ x) {
    int n4 = MT * DD / 4;
    int stride = gridDim.x * 256;
    for (int i = threadIdx.x + blockIdx.x * 256; i < n4; i += stride) {
        float4 v = reinterpret_cast<const float4*>(x)[i];
        __half2* d2 = reinterpret_cast<__half2*>(g_Xh) + (size_t)i * 2;
        d2[0] = __floats2half2_rn(v.x, v.y);
        d2[1] = __floats2half2_rn(v.z, v.w);
    }
}

// ---------------- gating stage A: 384 blocks, 16 rows each ----------------
__global__ void k_stageA(const float* __restrict__ x) {
    int b = blockIdx.x / NSC, c = blockIdx.x % NSC;
    const float* base = x + ((size_t)(b * LL + c * 16)) * DD;
    for (int d = threadIdx.x; d < DD; d += 256) {
        float s = 0.f;
        #pragma unroll
        for (int l = 0; l < 16; ++l) s += base[(size_t)l * DD + d];
        g_partial[(b * NSC + c) * DD + d] = s;
    }
}

// ---------------- weight transpose kernels (side stream s1) ----------------
// W==0: W1 family [D,H] -> [H,D] (z = 0..3 experts, z = 4 shared)
// W==1: W2 family [H,D] -> [D,H]
template<int W>
__global__ void k_convw(const float* __restrict__ src_e, const float* __restrict__ src_s) {
    int z = blockIdx.z;
    const float* src;
    __half* dst;
    int R = (W == 0) ? DD : HH;
    int C = (W == 0) ? HH : DD;
    if (z < NE) {
        src = src_e + (size_t)z * R * C;
        dst = ((W == 0) ? g_W1e : g_W2e) + (size_t)z * R * C;
    } else {
        src = src_s;
        dst = (W == 0) ? g_W1s : g_W2s;
    }
    int nCB = C / 64;
    int bx = blockIdx.x % nCB;
    int by = blockIdx.x / nCB;
    if (by >= R / 64) return;
    __shared__ float t[64][65];
    int c0 = bx * 64, r0 = by * 64;
    int tx = threadIdx.x, ty = threadIdx.y;
    #pragma unroll
    for (int j = 0; j < 8; j++) {
        int row = ty + j * 8;
        const float2* sp = reinterpret_cast<const float2*>(src + (size_t)(r0 + row) * C + c0);
        float2 v = sp[tx];              // cols 2tx, 2tx+1  (LDG.64)
        t[row][2 * tx]     = v.x;
        t[row][2 * tx + 1] = v.y;
    }
    __syncthreads();
    #pragma unroll
    for (int j = 0; j < 8; j++) {
        int cc = ty + j * 8;
        __half2 v = __floats2half2_rn(t[2 * tx][cc], t[2 * tx + 1][cc]);
        *reinterpret_cast<__half2*>(dst + (size_t)(c0 + cc) * R + r0 + 2 * tx) = v;
    }
}

// ---------------- gating stage B (shuffle reduction) ----------------
__global__ void k_gate(const float* __restrict__ gate_w, const float* __restrict__ gate_b,
                       const float* __restrict__ time_cond, const float* __restrict__ time_w,
                       const float* __restrict__ time_b)
{
    int b = blockIdx.x, t = threadIdx.x;
    int lane = t & 31, wrp = t >> 5;
    __shared__ float red[8][12];
    float acc[12];
    #pragma unroll
    for (int k = 0; k < 12; k++) acc[k] = 0.f;
    const float* pb = g_partial + (size_t)b * NSC * DD;
    for (int d = t; d < DD; d += 256) {
        float h = 0.f, w = 0.f, p = 0.f;
        #pragma unroll
        for (int c = 0; c < 16; c++) {
            h += pb[(0 * 16 + c) * DD + d];
            w += pb[(1 * 16 + c) * DD + d];
            p += pb[(2 * 16 + c) * DD + d];
        }
        float full = (h + w + p) * (1.f / 768.f);
        float hp   = (h + p) * (1.f / 512.f);
        float wp   = (w + p) * (1.f / 512.f);
        #pragma unroll
        for (int e = 0; e < 4; e++)
            acc[e] += full * gate_w[d*4+e] + hp * gate_w[(DD+d)*4+e] + wp * gate_w[(2*DD+d)*4+e];
        float tc = time_cond[b * DD + d];
        float s  = tc / (1.f + expf(-tc));   // silu
        #pragma unroll
        for (int j = 0; j < 8; j++) acc[4 + j] += s * time_w[d*8 + j];
    }
    // warp-level reduce all 12 accumulators
    #pragma unroll
    for (int k = 0; k < 12; k++) {
        #pragma unroll
        for (int o = 16; o > 0; o >>= 1)
            acc[k] += __shfl_xor_sync(0xffffffffu, acc[k], o);
    }
    if (lane == 0) {
        #pragma unroll
        for (int k = 0; k < 12; k++) red[wrp][k] = acc[k];
    }
    __syncthreads();
    if (t == 0) {
        float tot[12];
        #pragma unroll
        for (int k = 0; k < 12; k++) {
            float s = red[0][k];
            #pragma unroll
            for (int w2 = 1; w2 < 8; w2++) s += red[w2][k];
            tot[k] = s;
        }
        float logit[4], prob[4];
        #pragma unroll
        for (int e = 0; e < 4; e++) {
            float sc = tot[4 + e] + time_b[e];
            float sh = tot[8 + e] + time_b[4 + e];
            logit[e] = (tot[e] + gate_b[e]) * (1.f + sc) + sh;
        }
        float mx = fmaxf(fmaxf(logit[0], logit[1]), fmaxf(logit[2], logit[3]));
        float sum = 0.f;
        for (int e = 0; e < 4; e++) { prob[e] = expf(logit[e] - mx); sum += prob[e]; }
        for (int e = 0; e < 4; e++) prob[e] /= sum;
        int i1 = 0;
        for (int e = 1; e < 4; e++) if (prob[e] > prob[i1]) i1 = e;
        int i2 = -1;
        for (int e = 0; e < 4; e++) if (e != i1 && (i2 < 0 || prob[e] > prob[i2])) i2 = e;
        float denom = prob[i1] + prob[i2] + 1e-8f;
        #pragma unroll
        for (int e = 0; e < 4; e++) g_wbe[b * NE + e] = 0.f;
        g_wbe[b * NE + i1] = prob[i1] / denom;
        g_wbe[b * NE + i2] = prob[i2] / denom;
    }
}

// ---------------- GEMM1: 2 N-tiles per CTA, continuous 32-chunk pipeline ----------------
// H[z] = w * gelu(X @ W1[z] + b1[z]);  z = 0 shared, 1..4 experts
__global__ void __launch_bounds__(256, 2) k_mma1(
    const float* __restrict__ b_sh, const float* __restrict__ b_ex)
{
    constexpr int NCHT = DD / KCH;      // 16 chunks per tile
    constexpr int NT = 2;               // tiles per CTA
    constexpr int nch = NCHT * NT;      // 32 chunks total

    int bm = blockIdx.x, bn0 = blockIdx.y * NT, z = blockIdx.z;
    float w = tile_weight(z - 1, bm);
    if (w == 0.f) return;

    const __half* A = g_Xh;
    const __half* B = (z == 0) ? g_W1s : (g_W1e + (size_t)(z - 1) * HH * DD);
    const float* bias = (z == 0) ? b_sh : (b_ex + (size_t)(z - 1) * HH);
    __half* hout = g_H + (size_t)z * MT * HH;

    extern __shared__ __align__(128) char smem[];
    uint32_t sbase = smem_u32(smem);
    int tid = threadIdx.x, lane = tid & 31, wid = tid >> 5;
    int wm = wid & 3, wn = wid >> 2;
    int m0 = bm * 128;

    auto issue = [&](int flat, int slot) {
        int tile  = flat >> 4;          // 0..1
        int chunk = flat & (NCHT - 1);
        int koff = chunk * KCH;
        int n0 = (bn0 + tile) * 128;
        const __half* Ab = A + koff;
        const __half* Bb = B + koff;
        char* st = smem + slot * STG_BYTES;
        #pragma unroll
        for (int i = 0; i < 4; i++) {
            int idx = tid + i * 256;
            int r = idx >> 3, c8 = idx & 7;
            uint32_t off = (uint32_t)(r * 128 + c8 * 16);
            off ^= (off >> 3) & 0x70;
            cp_async16(st + off, Ab + (size_t)(m0 + r) * DD + c8 * 8);
        }
        #pragma unroll
        for (int i = 0; i < 4; i++) {
            int idx = tid + i * 256;
            int r = idx >> 3, c8 = idx & 7;
            uint32_t off = (uint32_t)(r * 128 + c8 * 16);
            off ^= (off >> 3) & 0x70;
            cp_async16(st + TILE_BYTES + off, Bb + (size_t)(n0 + r) * DD + c8 * 8);
        }
        cp_commit();
    };

    float c[2][8][4];
    #pragma unroll
    for (int i = 0; i < 2; i++)
        #pragma unroll
        for (int j = 0; j < 8; j++)
            #pragma unroll
            for (int q = 0; q < 4; q++) c[i][j][q] = 0.f;

    int gid = lane >> 2, tig = lane & 3;
    auto epilogue = [&](int tile) {
        int n0 = (bn0 + tile) * 128;
        #pragma unroll
        for (int i = 0; i < 2; i++) {
            int r0i = m0 + wm * 32 + i * 16 + gid;
            #pragma unroll
            for (int j = 0; j < 8; j++) {
                int col = n0 + wn * 64 + j * 8 + tig * 2;
                float b0 = __ldg(bias + col);
                float b1 = __ldg(bias + col + 1);
                __half2 h0 = __floats2half2_rn(w * gelu_t(c[i][j][0] + b0),
                                               w * gelu_t(c[i][j][1] + b1));
                __half2 h1 = __floats2half2_rn(w * gelu_t(c[i][j][2] + b0),
                                               w * gelu_t(c[i][j][3] + b1));
                *reinterpret_cast<__half2*>(hout + (size_t)r0i * HH + col) = h0;
                *reinterpret_cast<__half2*>(hout + (size_t)(r0i + 8) * HH + col) = h1;
                c[i][j][0] = c[i][j][1] = c[i][j][2] = c[i][j][3] = 0.f;   // reset for next tile
            }
        }
    };

    issue(0, 0);
    issue(1, 1);

    for (int it = 0; it < nch; ++it) {
        if (it + 1 < nch) asm volatile("cp.async.wait_group 1;" ::: "memory");
        else              asm volatile("cp.async.wait_group 0;" ::: "memory");
        __syncthreads();
        if (it + 2 < nch) issue(it + 2, (it + 2) % SS);

        uint32_t sAb = sbase + (it % SS) * STG_BYTES;
        uint32_t sBb = sAb + TILE_BYTES;
        #pragma unroll
        for (int kk = 0; kk < 4; kk++) {
            uint32_t a[2][4];
            #pragma unroll
            for (int i = 0; i < 2; i++) {
                int row = wm * 32 + i * 16 + (lane & 15);
                uint32_t off = (uint32_t)(row * 128 + kk * 32 + ((lane >> 4) & 1) * 16);
                off ^= (off >> 3) & 0x70;
                ldm4(a[i], sAb + off);
            }
            uint32_t b[8][2];
            #pragma unroll
            for (int jp = 0; jp < 4; jp++) {
                int n = wn * 64 + jp * 16 + ((lane >> 4) & 1) * 8 + (lane & 7);
                uint32_t off = (uint32_t)(n * 128 + kk * 32 + ((lane >> 3) & 1) * 16);
                off ^= (off >> 3) & 0x70;
                uint32_t r4[4];
                ldm4(r4, sBb + off);
                b[2 * jp][0] = r4[0]; b[2 * jp][1] = r4[1];
                b[2 * jp + 1][0] = r4[2]; b[2 * jp + 1][1] = r4[3];
            }
            #pragma unroll
            for (int i = 0; i < 2; i++)
                #pragma unroll
                for (int j = 0; j < 8; j++)
                    mma16816(c[i][j], a[i], b[j]);
        }
        if ((it & (NCHT - 1)) == NCHT - 1)
            epilogue(it >> 4);          // mid-stream epilogue; loads for next tile already in flight
    }
}

// ---------------- GEMM2: split-K(2) x segment-concat. P[zk] = sum over segs, K-half zk ----------------
__global__ void __launch_bounds__(256, 2) k_mma2()
{
    int bm = blockIdx.x, bn = blockIdx.y, zk = blockIdx.z;   // zk in {0,1}
    __shared__ const __half* sA[1 + NE];
    __shared__ const __half* sB[1 + NE];
    __shared__ int sNs;

    if (threadIdx.x == 0) {
        int ns = 0;
        sA[ns] = g_H; sB[ns] = g_W2s; ns++;
        for (int e = 0; e < NE; e++) {
            if (tile_weight(e, bm) > 0.f) {
                sA[ns] = g_H + (size_t)(e + 1) * MT * HH;
                sB[ns] = g_W2e + (size_t)e * DD * HH;
                ns++;
            }
        }
        sNs = ns;
    }
    __syncthreads();
    int ns = sNs;
    int nch = ns * 32;                  // 32 chunks = K-half (2048) per segment
    int kbase = zk * 2048;

    extern __shared__ __align__(128) char smem[];
    uint32_t sbase = smem_u32(smem);
    int tid = threadIdx.x, lane = tid & 31, wid = tid >> 5;
    int wm = wid & 3, wn = wid >> 2;
    int m0 = bm * 128, n0 = bn * 128;
    float* pout = g_P + (size_t)zk * MT * DD;

    auto issue = [&](int flat, int slot) {
        int seg = flat >> 5;
        int koff = kbase + (flat & 31) * KCH;
        const __half* Ab = sA[seg] + koff;
        const __half* Bb = sB[seg] + koff;
        char* st = smem + slot * STG_BYTES;
        #pragma unroll
        for (int i = 0; i < 4; i++) {
            int idx = tid + i * 256;
            int r = idx >> 3, c8 = idx & 7;
            uint32_t off = (uint32_t)(r * 128 + c8 * 16);
            off ^= (off >> 3) & 0x70;
            cp_async16(st + off, Ab + (size_t)(m0 + r) * HH + c8 * 8);
        }
        #pragma unroll
        for (int i = 0; i < 4; i++) {
            int idx = tid + i * 256;
            int r = idx >> 3, c8 = idx & 7;
            uint32_t off = (uint32_t)(r * 128 + c8 * 16);
            off ^= (off >> 3) & 0x70;
            cp_async16(st + TILE_BYTES + off, Bb + (size_t)(n0 + r) * HH + c8 * 8);
        }
        cp_commit();
    };

    float c[2][8][4];
    #pragma unroll
    for (int i = 0; i < 2; i++)
        #pragma unroll
        for (int j = 0; j < 8; j++)
            #pragma unroll
            for (int q = 0; q < 4; q++) c[i][j][q] = 0.f;

    issue(0, 0);
    issue(1, 1);

    for (int it = 0; it < nch; ++it) {
        if (it + 1 < nch) asm volatile("cp.async.wait_group 1;" ::: "memory");
        else              asm volatile("cp.async.wait_group 0;" ::: "memory");
        __syncthreads();
        if (it + 2 < nch) issue(it + 2, (it + 2) % SS);

        uint32_t sAb = sbase + (it % SS) * STG_BYTES;
        uint32_t sBb = sAb + TILE_BYTES;
        #pragma unroll
        for (int kk = 0; kk < 4; kk++) {
            uint32_t a[2][4];
            #pragma unroll
            for (int i = 0; i < 2; i++) {
                int row = wm * 32 + i * 16 + (lane & 15);
                uint32_t off = (uint32_t)(row * 128 + kk * 32 + ((lane >> 4) & 1) * 16);
                off ^= (off >> 3) & 0x70;
                ldm4(a[i], sAb + off);
            }
            uint32_t b[8][2];
            #pragma unroll
            for (int jp = 0; jp < 4; jp++) {
                int n = wn * 64 + jp * 16 + ((lane >> 4) & 1) * 8 + (lane & 7);
                uint32_t off = (uint32_t)(n * 128 + kk * 32 + ((lane >> 3) & 1) * 16);
                off ^= (off >> 3) & 0x70;
                uint32_t r4[4];
                ldm4(r4, sBb + off);
                b[2 * jp][0] = r4[0]; b[2 * jp][1] = r4[1];
                b[2 * jp + 1][0] = r4[2]; b[2 * jp + 1][1] = r4[3];
            }
            #pragma unroll
            for (int i = 0; i < 2; i++)
                #pragma unroll
                for (int j = 0; j < 8; j++)
                    mma16816(c[i][j], a[i], b[j]);
        }
    }

    int gid = lane >> 2, tig = lane & 3;
    #pragma unroll
    for (int i = 0; i < 2; i++) {
        int r0i = m0 + wm * 32 + i * 16 + gid;
        #pragma unroll
        for (int j = 0; j < 8; j++) {
            int col = n0 + wn * 64 + j * 8 + tig * 2;
            *reinterpret_cast<float2*>(pout + (size_t)r0i * DD + col) =
                make_float2(c[i][j][0], c[i][j][1]);
            *reinterpret_cast<float2*>(pout + (size_t)(r0i + 8) * DD + col) =
                make_float2(c[i][j][2], c[i][j][3]);
        }
    }
}

// ---------------- reduce: out = P0 + P1 + b_sh + sum_e w*mask*b2_e ----------------
__global__ void k_reduce(const float* __restrict__ b_sh, const float* __restrict__ b_ex,
                         float* __restrict__ out)
{
    int bm = blockIdx.x;
    int bn = blockIdx.y;
    float we[NE];
    #pragma unroll
    for (int e = 0; e < NE; e++) we[e] = tile_weight(e, bm);

    int tid = threadIdx.x;
    size_t base = (size_t)bm * 128 * DD + bn * 128;
    for (int q = tid; q < 4096; q += 256) {
        int r = q >> 5;
        int c4 = (q & 31) << 2;
        size_t off = base + (size_t)r * DD + c4;
        int col = bn * 128 + c4;
        float4 acc = *reinterpret_cast<const float4*>(g_P + off);
        float4 p1  = *reinterpret_cast<const float4*>(g_P + (size_t)MT * DD + off);
        float4 bs  = *reinterpret_cast<const float4*>(b_sh + col);
        acc.x += p1.x + bs.x; acc.y += p1.y + bs.y;
        acc.z += p1.z + bs.z; acc.w += p1.w + bs.w;
        #pragma unroll
        for (int e = 0; e < NE; e++) {
            if (we[e] > 0.f) {
                float4 be = *reinterpret_cast<const float4*>(b_ex + (size_t)e * DD + col);
                acc.x += we[e] * be.x; acc.y += we[e] * be.y;
                acc.z += we[e] * be.z; acc.w += we[e] * be.w;
            }
        }
        *reinterpret_cast<float4*>(out + off) = acc;
    }
}

// ---------------- launch ----------------
extern "C" void kernel_launch(void* const* d_in, const int* in_sizes, int n_in,
                              void* d_out, int out_size)
{
    (void)in_sizes; (void)n_in; (void)out_size;
    const float* x         = (const float*)d_in[0];
    const float* time_cond = (const float*)d_in[1];
    const float* gate_w    = (const float*)d_in[2];
    const float* gate_b    = (const float*)d_in[3];
    const float* time_w    = (const float*)d_in[4];
    const float* time_b    = (const float*)d_in[5];
    const float* ew1       = (const float*)d_in[6];
    const float* eb1       = (const float*)d_in[7];
    const float* ew2       = (const float*)d_in[8];
    const float* eb2       = (const float*)d_in[9];
    const float* sw1       = (const float*)d_in[10];
    const float* sb1       = (const float*)d_in[11];
    const float* sw2       = (const float*)d_in[12];
    const float* sb2       = (const float*)d_in[13];
    float* out = (float*)d_out;

    // one-time host resources (no device memory involved)
    static cudaStream_t s1 = nullptr, s2 = nullptr;
    static cudaEvent_t ev_fork = nullptr, ev_w1 = nullptr, ev_w2 = nullptr, ev_x = nullptr;
    if (s1 == nullptr) {
        cudaStreamCreateWithFlags(&s1, cudaStreamNonBlocking);
        cudaStreamCreateWithFlags(&s2, cudaStreamNonBlocking);
        cudaEventCreateWithFlags(&ev_fork, cudaEventDisableTiming);
        cudaEventCreateWithFlags(&ev_w1,   cudaEventDisableTiming);
        cudaEventCreateWithFlags(&ev_w2,   cudaEventDisableTiming);
        cudaEventCreateWithFlags(&ev_x,    cudaEventDisableTiming);
        cudaFuncSetAttribute(k_mma1, cudaFuncAttributeMaxDynamicSharedMemorySize, GEMM_SMEM);
        cudaFuncSetAttribute(k_mma2, cudaFuncAttributeMaxDynamicSharedMemorySize, GEMM_SMEM);
    }

    // fork side streams from the main (capture-origin) stream
    cudaEventRecord(ev_fork, 0);
    cudaStreamWaitEvent(s1, ev_fork, 0);
    cudaStreamWaitEvent(s2, ev_fork, 0);

    // s1: weight transposes (W1 first — GEMM1 dependency; W2 hides under GEMM1)
    k_convw<0><<<dim3(1024, 1, NE + 1), dim3(32, 8), 0, s1>>>(ew1, sw1);
    cudaEventRecord(ev_w1, s1);
    k_convw<1><<<dim3(1024, 1, NE + 1), dim3(32, 8), 0, s1>>>(ew2, sw2);
    cudaEventRecord(ev_w2, s1);

    // s2: x fp32 -> fp16
    k_convx<<<1024, 256, 0, s2>>>(x);
    cudaEventRecord(ev_x, s2);

    // main stream: gating (stage A then B)
    k_stageA<<<NB * NSC, 256>>>(x);
    k_gate<<<8, 256>>>(gate_w, gate_b, time_cond, time_w, time_b);

    // GEMM1 needs gate + Xh + W1 transposes
    cudaStreamWaitEvent(0, ev_x, 0);
    cudaStreamWaitEvent(0, ev_w1, 0);
    k_mma1<<<dim3(MT / 128, HH / 256, 5), 256, GEMM_SMEM>>>(sb1, eb1);

    // GEMM2 needs W2 transposes (overlapped with GEMM1)
    cudaStreamWaitEvent(0, ev_w2, 0);
    k_mma2<<<dim3(MT / 128, DD / 128, KSPLIT), 256, GEMM_SMEM>>>();

    // combine partials + biases into out (single deterministic write)
    k_reduce<<<dim3(MT / 128, DD / 128), 256>>>(sb2, eb2, out);
}